// round 13
// baseline (speedup 1.0000x reference)
#include <cuda_runtime.h>
#include <cuda_bf16.h>
#include <math.h>
#include <stdint.h>

#define BB 8
#define NQ 1024
#define NK 256
#define HH 8
#define DF 528
#define DFP 576
#define DX 544

typedef unsigned long long u64;
typedef unsigned int u32;

__constant__ int c_cg[11]    = {0,1,1,1,2,2,2,3,3,3,3};
__constant__ int c_comps[11] = {0,2,3,4,8,9,10,14,11,12,13};
__constant__ int c_grade[16] = {0,1,1,1,1,2,2,2,2,2,2,3,3,3,3,4};

__device__ float g_WqT [5*48*384];
__device__ float g_WkvT[5*48*768];
__device__ float g_WoT [5*384*48];
__device__ float g_sp  [8];
__device__ __nv_bfloat16 g_xfeat [(size_t)BB*NQ*DX];
__device__ __nv_bfloat16 g_M     [(size_t)BB*HH*NK*DX];
__device__ float         g_kfeatT[(size_t)BB*HH*NK*DFP];
__device__ float         g_vtmp  [(size_t)BB*HH*16*12288];
__device__ __nv_bfloat16 g_vprojT[(size_t)BB*768*2048];
__device__ __nv_bfloat16 g_attn  [(size_t)BB*NQ*2048];

__device__ __forceinline__ u64 pk2(float lo, float hi){
    u64 u; asm("mov.b64 %0,{%1,%2};" : "=l"(u) : "f"(lo), "f"(hi)); return u;
}
__device__ __forceinline__ void upk2(u64 u, float& lo, float& hi){
    asm("mov.b64 {%0,%1},%2;" : "=f"(lo), "=f"(hi) : "l"(u));
}
__device__ __forceinline__ u64 f2fma(u64 a, u64 b, u64 c){
    u64 d; asm("fma.rn.f32x2 %0,%1,%2,%3;" : "=l"(d) : "l"(a), "l"(b), "l"(c)); return d;
}
__device__ __forceinline__ u32 bf2(float lo, float hi){
    u32 r; asm("cvt.rn.bf16x2.f32 %0,%1,%2;" : "=r"(r) : "f"(hi), "f"(lo)); return r;
}
__device__ __forceinline__ u32 smem_u32(const void* p){
    u32 a; asm("{ .reg .u64 t; cvta.to.shared.u64 t, %1; cvt.u32.u64 %0, t; }" : "=r"(a) : "l"(p));
    return a;
}
__device__ __forceinline__ void mma16816(float* d, const u32* a, const u32* b){
    asm volatile("mma.sync.aligned.m16n8k16.row.col.f32.bf16.bf16.f32 "
        "{%0,%1,%2,%3},{%4,%5,%6,%7},{%8,%9},{%0,%1,%2,%3};"
        : "+f"(d[0]), "+f"(d[1]), "+f"(d[2]), "+f"(d[3])
        : "r"(a[0]), "r"(a[1]), "r"(a[2]), "r"(a[3]), "r"(b[0]), "r"(b[1]));
}
__device__ __forceinline__ void ldsm4(u32& r0, u32& r1, u32& r2, u32& r3, u32 addr){
    asm volatile("ldmatrix.sync.aligned.m8n8.x4.shared.b16 {%0,%1,%2,%3},[%4];"
        : "=r"(r0), "=r"(r1), "=r"(r2), "=r"(r3) : "r"(addr));
}
__device__ __forceinline__ void cp16(u32 sdst, const void* gsrc){
    asm volatile("cp.async.cg.shared.global [%0], [%1], 16;" :: "r"(sdst), "l"(gsrc));
}

// ============ K0a: WqT + WoT transposes + softplus ==========================
__global__ void k0a_prep(const float* __restrict__ Wq, const float* __restrict__ Wo,
                         const float* __restrict__ daa){
    int stride = gridDim.x * blockDim.x;
    int gid = blockIdx.x * blockDim.x + threadIdx.x;
    for (int idx = gid; idx < 5*384*48; idx += stride){
        int g = idx/(384*48), rem = idx%(384*48), o = rem/48, i = rem%48;
        g_WqT[(g*48+i)*384+o] = Wq[idx];
    }
    for (int idx = gid; idx < 5*48*384; idx += stride){
        int g = idx/(48*384), rem = idx%(48*384), o = rem/384, i = rem%384;
        g_WoT[(g*384+i)*48+o] = Wo[idx];
    }
    if (gid < 8){
        float x = daa[gid];
        g_sp[gid] = (x > 20.f) ? x : log1pf(expf(x));
    }
}

// ============ K0b: WkvT transpose ===========================================
__global__ void k0b_prep(const float* __restrict__ Wkv){
    int stride = gridDim.x * blockDim.x;
    int gid = blockIdx.x * blockDim.x + threadIdx.x;
    for (int idx = gid; idx < 5*768*48; idx += stride){
        int g = idx/(768*48), rem = idx%(768*48), o = rem/48, i = rem%48;
        g_WkvT[(g*48+i)*768+o] = Wkv[idx];
    }
}

// ============ K2x: rmsnorm + reorder -> xfeat [row][544] (bf16) =============
__global__ void __launch_bounds__(256) k2x_xfeat(const float* __restrict__ hidden,
                                                 const float* __restrict__ lnw){
    extern __shared__ float sx[];
    float* rows = sx;               // 16*768
    float* rsq  = sx + 16*768;      // 16
    int b = blockIdx.y, q0 = blockIdx.x*16, t = threadIdx.x;
    const float* hrow = hidden + (size_t)(b*NQ+q0)*768;
    for (int idx = t; idx < 16*768; idx += 256) rows[idx] = hrow[idx];
    __syncthreads();
    { int r = t>>4, sub = t&15; float s = 0.f;
      for (int e = sub; e < 768; e += 16){ float v = rows[r*768+e]; s += v*v; }
      s += __shfl_xor_sync(~0u, s, 1);
      s += __shfl_xor_sync(~0u, s, 2);
      s += __shfl_xor_sync(~0u, s, 4);
      s += __shfl_xor_sync(~0u, s, 8);
      if (sub == 0) rsq[r] = rsqrtf(s*(1.f/48.f) + 1e-6f);
    }
    __syncthreads();
    __nv_bfloat16* dst = g_xfeat + (size_t)(b*NQ+q0)*DX;
    for (int idx = t; idx < 16*DX; idx += 256){
        int r = idx/DX, d = idx - r*DX;
        float val;
        if (d < DF){
            int js = d/48, in = d - js*48;
            val = rows[r*768 + in*16 + c_comps[js]] * rsq[r] * lnw[in];
        } else val = (d == DF) ? 1.f : 0.f;
        dst[idx] = __float2bfloat16(val);
    }
}

// ========== K1a v3: kv projection; grid (ktile, ohalf*2+chalf, b) ===========
__global__ void __launch_bounds__(256) k1a_kv(const float* __restrict__ vision,
                                              const float* __restrict__ bkv){
    extern __shared__ float sm1[];
    float* xT = sm1;            // [(cl*48+in)][key16] pad 18 -> 384*18
    int b = blockIdx.z, y = blockIdx.y, k0 = blockIdx.x*16, t = threadIdx.x;
    int ohalf = y >> 1, chalf = y & 1;

    for (int idx = t; idx < 16*384; idx += 256){
        int key = idx/384, r = idx - key*384, in = r>>3, cl = r&7;
        xT[(cl*48+in)*18 + key] =
            vision[((size_t)(b*NK + k0 + key))*768 + in*16 + chalf*8 + cl];
    }
    __syncthreads();

    const float INVS = 0.051031036307982884f;  // 1/sqrt(384)
    const int GRL_T[16] = {0,1,1,1,1,2,2,2, 0,0,0,1,1,1,1,2};
    int grl[8];
    #pragma unroll
    for (int cl = 0; cl < 8; cl++) grl[cl] = GRL_T[chalf*8 + cl];

    int o = ohalf*256 + t;
    float bias = bkv[o];
    const float* wb = g_WkvT + (size_t)(chalf*2*48)*768 + o;
    for (int kt = 0; kt < 4; kt++){
        u64 acc[2][8];
        #pragma unroll
        for (int kp = 0; kp < 2; kp++){
            acc[kp][0] = (chalf == 0) ? pk2(bias, bias) : 0ull;
            #pragma unroll
            for (int cl = 1; cl < 8; cl++) acc[kp][cl] = 0ull;
        }
        #pragma unroll 4
        for (int in = 0; in < 48; in++){
            float w0 = wb[(0*48+in)*768];
            float w1 = wb[(1*48+in)*768];
            float w2 = wb[(2*48+in)*768];
            u64 wv[3] = {pk2(w0,w0), pk2(w1,w1), pk2(w2,w2)};
            #pragma unroll
            for (int cl = 0; cl < 8; cl++){
                const float* xp = xT + (cl*48+in)*18 + kt*4;
                acc[0][cl] = f2fma(*(const u64*)(xp    ), wv[grl[cl]], acc[0][cl]);
                acc[1][cl] = f2fma(*(const u64*)(xp + 2), wv[grl[cl]], acc[1][cl]);
            }
        }
        if (o < 384){
            int h = o/48, i = o - h*48;
            float sp = g_sp[h], spc = sp*(2.f/48.f);
            size_t rb = (size_t)((b*HH+h)*NK + k0 + kt*4)*DFP;
            if (chalf == 0){
                const int LIC[4] = {0,2,3,4};     // comps 0,2,3,4 -> js 0..3
                #pragma unroll
                for (int jj = 0; jj < 4; jj++)
                    #pragma unroll
                    for (int kp = 0; kp < 2; kp++){
                        float lo, hi; upk2(acc[kp][LIC[jj]], lo, hi);
                        g_kfeatT[rb + (size_t)(2*kp  )*DFP + jj*48+i] = lo*INVS;
                        g_kfeatT[rb + (size_t)(2*kp+1)*DFP + jj*48+i] = hi*INVS;
                    }
            } else {
                const int LIC[4] = {0,1,2,6};     // comps 8,9,10,14 -> js 4..7
                #pragma unroll
                for (int jj = 0; jj < 4; jj++)
                    #pragma unroll
                    for (int kp = 0; kp < 2; kp++){
                        float lo, hi; upk2(acc[kp][LIC[jj]], lo, hi);
                        g_kfeatT[rb + (size_t)(2*kp  )*DFP + (4+jj)*48+i] = lo*INVS;
                        g_kfeatT[rb + (size_t)(2*kp+1)*DFP + (4+jj)*48+i] = hi*INVS;
                    }
                const int LPC[3] = {3,4,5};       // comps 11,12,13 -> jp 0..2
                #pragma unroll
                for (int jp = 0; jp < 3; jp++)
                    #pragma unroll
                    for (int kp = 0; kp < 2; kp++){
                        float lo, hi; upk2(acc[kp][LPC[jp]], lo, hi);
                        g_kfeatT[rb + (size_t)(2*kp  )*DFP + 384+jp*48+i] = lo*spc;
                        g_kfeatT[rb + (size_t)(2*kp+1)*DFP + 384+jp*48+i] = hi*spc;
                    }
            }
        } else {
            int vc = o - 384, h = vc/48, i = vc - h*48;
            float* vb = g_vtmp + ((size_t)((b*HH+h)*16 + (k0>>4)))*12288 + i*256 + kt*4;
            #pragma unroll
            for (int cl = 0; cl < 8; cl++){
                int c = chalf*8 + cl;
                *(u64*)&vb[c*16]     = acc[0][cl];
                *(u64*)&vb[c*16 + 2] = acc[1][cl];
            }
        }
    }
}

// ========== K1b: vprojT via cp.async double-buffered subtiles ===============
__device__ __forceinline__ void k1b_stage(int t, u32 sb, const float* Vg, int s){
    const float* src = Vg + (size_t)(s>>1)*12288 + (s&1)*8;
    u32 dst = sb + (u32)((s&1)*6144)*4;
    #pragma unroll
    for (int it = 0; it < 6; it++){
        int idx = t + 256*it;            // 1536 chunks of 16B
        int row = idx>>1, part = idx&1;
        cp16(dst + (u32)(row*8 + part*4)*4, src + row*16 + part*4);
    }
    asm volatile("cp.async.commit_group;" ::: "memory");
}

__global__ void __launch_bounds__(256) k1b_vproj(){
    extern __shared__ float sm2[];
    float* w_s = sm2;             // 11520
    float* v_s = sm2 + 11520;     // 2 * 6144
    int sl = blockIdx.x, h = blockIdx.y, b = blockIdx.z, t = threadIdx.x;

    for (int idx = t; idx < 11520; idx += 256){
        int g = idx/2304, r = idx - g*2304;
        w_s[idx] = g_WoT[(g*384 + h*48)*48 + r];
    }
    int j = sl*256 + t;
    int o48 = j % 48, c = j / 48;
    int g = c_grade[c];
    const float* Vg = g_vtmp + (size_t)((b*HH+h)*16)*12288;
    u32 sb = smem_u32(v_s);
    const float* wp = w_s + g*2304 + o48;

    k1b_stage(t, sb, Vg, 0);
    for (int s = 0; s < 32; s++){
        if (s + 1 < 32){
            k1b_stage(t, sb, Vg, s+1);
            asm volatile("cp.async.wait_group 1;" ::: "memory");
        } else {
            asm volatile("cp.async.wait_group 0;" ::: "memory");
        }
        __syncthreads();
        const float* vp0 = v_s + (s&1)*6144 + c*8;
        u64 acc[4] = {0ull, 0ull, 0ull, 0ull};
        #pragma unroll 8
        for (int i = 0; i < 48; i++){
            float w = wp[i*48];
            u64 w2 = pk2(w, w);
            const float* vp = vp0 + i*128;
            acc[0] = f2fma(*(const u64*)(vp    ), w2, acc[0]);
            acc[1] = f2fma(*(const u64*)(vp + 2), w2, acc[1]);
            acc[2] = f2fma(*(const u64*)(vp + 4), w2, acc[2]);
            acc[3] = f2fma(*(const u64*)(vp + 6), w2, acc[3]);
        }
        u32 r4[4];
        #pragma unroll
        for (int kp = 0; kp < 4; kp++){
            float lo, hi; upk2(acc[kp], lo, hi);
            r4[kp] = bf2(lo, hi);
        }
        __nv_bfloat16* dst = g_vprojT + (size_t)(b*768 + o48*16 + c)*2048
                           + h*256 + (s>>1)*16 + (s&1)*8;
        *(uint4*)dst = *(const uint4*)r4;
        __syncthreads();
    }
}

// ======= K2m: M[b,h][k][544] (bf16) — 512 CTAs, 32 keys each ================
__global__ void __launch_bounds__(256) k2m_M(const float* __restrict__ bq){
    __shared__ float kfT[48*34];   // [j][key32] pad 34
    __shared__ float ws [48*49];   // [j][c] pad 49
    __shared__ float mT [48*34];   // [c][key32] pad 34
    __shared__ float kb32[32];
    __shared__ float ss32[32];
    int kt0 = blockIdx.x*32, h = blockIdx.y, b = blockIdx.z, t = threadIdx.x;
    size_t kbase = (size_t)((b*HH+h)*NK) + kt0;
    if (t < 32) ss32[t] = 0.f;

    for (int js = 0; js < 11; js++){
        int g = c_cg[js];
        __syncthreads();
        #pragma unroll
        for (int r = 0; r < 6; r++){
            int idx = t + 256*r;                // 48*32 = 1536
            if (idx < 1536){
                int k = idx/48, j = idx - k*48;
                kfT[j*34 + k] = g_kfeatT[(kbase + k)*DFP + js*48 + j];
            }
        }
        #pragma unroll
        for (int r = 0; r < 9; r++){
            int idx = t + 256*r;                // 2304
            if (idx < 2304){
                int c = idx/48, j = idx - c*48;
                ws[j*49 + c] = g_WqT[(g*48+c)*384 + h*48 + j];
            }
        }
        __syncthreads();
        if (js == 0 && t < 32){
            float s = 0.f;
            #pragma unroll 8
            for (int j = 0; j < 48; j++) s += bq[h*48+j]*kfT[j*34 + t];
            kb32[t] = s;
        }
        if (js >= 8 && t < 32){
            float s = 0.f;
            #pragma unroll 8
            for (int j = 0; j < 48; j++){ float v = kfT[j*34 + t]; s += v*v; }
            ss32[t] += s;
        }
        #pragma unroll
        for (int r = 0; r < 3; r++){
            int o = t + 256*r;                  // 768 = 48c * 16 keypairs
            int c = o >> 4, kp = o & 15;
            u64 acc = 0ull;
            #pragma unroll 8
            for (int j = 0; j < 48; j++){
                float w = ws[j*49 + c];
                acc = f2fma(*(const u64*)&kfT[j*34 + 2*kp], pk2(w, w), acc);
            }
            *(u64*)&mT[c*34 + 2*kp] = acc;
        }
        __syncthreads();
        #pragma unroll
        for (int r = 0; r < 6; r++){
            int idx = t + 256*r;
            if (idx < 1536){
                int k = idx/48, c = idx - k*48;
                g_M[(kbase + k)*DX + js*48 + c] = __float2bfloat16(mT[c*34 + k]);
            }
        }
    }
    __syncthreads();
    float sp = g_sp[h];
    #pragma unroll
    for (int r = 0; r < 2; r++){
        int idx = t + 256*r;                    // 32*16 = 512
        int k = idx >> 4, cc = idx & 15;
        float v = (cc == 0) ? (kb32[k] - (12.f/sp)*ss32[k]) : 0.f;
        g_M[(kbase + k)*DX + DF + cc] = __float2bfloat16(v);
    }
}

// ============ bf16 GEMM core: 64 rows x 256 cols, ldmatrix + mma16816 =======
#define AROW 20
#define BOFF 1280
#define BUFU 6400

__device__ __forceinline__ void gemm_chunk(u32 base, float acc[4][4][4],
                                           int wid, u32 aofs, u32 bofs){
    #pragma unroll
    for (int k16 = 0; k16 < 2; k16++){
        int ko = k16*8;
        u32 au[4][4];
        #pragma unroll
        for (int mt = 0; mt < 4; mt++)
            ldsm4(au[mt][0], au[mt][1], au[mt][2], au[mt][3],
                  base + (u32)(mt*16*AROW + ko)*4 + aofs);
        u32 bu[4][2];
        ldsm4(bu[0][0], bu[0][1], bu[1][0], bu[1][1],
              base + (u32)(BOFF + wid*32*AROW + ko)*4 + bofs);
        ldsm4(bu[2][0], bu[2][1], bu[3][0], bu[3][1],
              base + (u32)(BOFF + (wid*32+16)*AROW + ko)*4 + bofs);
        #pragma unroll
        for (int mt = 0; mt < 4; mt++)
            #pragma unroll
            for (int nt8 = 0; nt8 < 4; nt8++)
                mma16816(acc[mt][nt8], au[mt], bu[nt8]);
    }
}

__device__ __forceinline__ void stage_tile(int t, u32 sb, const __nv_bfloat16* Ag,
                                           const __nv_bfloat16* Bg, int kc, int stride){
    { int row = t>>2, seg = t&3;
      cp16(sb + (u32)(row*AROW + seg*4)*4, Ag + (size_t)row*stride + kc*32 + seg*8); }
    #pragma unroll
    for (int it = 0; it < 4; it++){
        int i = t + 256*it, row = i>>2, seg = i&3;
        cp16(sb + (u32)(BOFF + row*AROW + seg*4)*4, Bg + (size_t)row*stride + kc*32 + seg*8);
    }
    asm volatile("cp.async.commit_group;" ::: "memory");
}

// ===================== K2b: bf16 mma logits + softmax ======================
__global__ void __launch_bounds__(256, 2) k2b_logits(){
    extern __shared__ u32 smp[];
    float* red  = (float*)(smp + 3*BUFU);   // 512
    float* rmax = red + 512;
    float* rsum = rmax + 64;
    int t = threadIdx.x, wid = t>>5, lane = t&31;
    int g = lane>>2, t4 = lane&3;
    int qt = blockIdx.x, h = blockIdx.y, b = blockIdx.z;

    u32 aofs = (u32)((((lane&7) + ((lane>>3)&1)*8)*AROW + ((lane>>4)&1)*4)*4);
    u32 bofs = (u32)(((((lane>>4)&1)*8 + (lane&7))*AROW + ((lane>>3)&1)*4)*4);

    const __nv_bfloat16* Ag = g_xfeat + (size_t)(b*NQ + qt*64)*DX;
    const __nv_bfloat16* Bg = g_M     + (size_t)((b*HH+h)*NK)*DX;
    u32 sb = smem_u32(smp);

    float acc[4][4][4];
    #pragma unroll
    for (int mt = 0; mt < 4; mt++)
        #pragma unroll
        for (int nt8 = 0; nt8 < 4; nt8++)
            #pragma unroll
            for (int r = 0; r < 4; r++) acc[mt][nt8][r] = 0.f;

    stage_tile(t, sb, Ag, Bg, 0, DX);
    stage_tile(t, sb + BUFU*4, Ag, Bg, 1, DX);
    for (int kc = 0; kc < 17; kc++){
        asm volatile("cp.async.wait_group 1;" ::: "memory");
        __syncthreads();
        if (kc + 2 < 17)
            stage_tile(t, sb + (u32)(((kc+2)%3)*BUFU)*4, Ag, Bg, kc+2, DX);
        else
            asm volatile("cp.async.commit_group;" ::: "memory");
        gemm_chunk(sb + (u32)((kc%3)*BUFU)*4, acc, wid, aofs, bofs);
    }

    __syncthreads();
    #pragma unroll
    for (int mt = 0; mt < 4; mt++)
        #pragma unroll
        for (int i = 0; i < 2; i++){
            float m = -1e30f;
            #pragma unroll
            for (int nt8 = 0; nt8 < 4; nt8++)
                m = fmaxf(m, fmaxf(acc[mt][nt8][2*i], acc[mt][nt8][2*i+1]));
            m = fmaxf(m, __shfl_xor_sync(~0u, m, 1));
            m = fmaxf(m, __shfl_xor_sync(~0u, m, 2));
            if (t4 == 0) red[(mt*16 + g + i*8)*8 + wid] = m;
        }
    __syncthreads();
    if (t < 64){
        float m = red[t*8];
        #pragma unroll
        for (int j = 1; j < 8; j++) m = fmaxf(m, red[t*8+j]);
        rmax[t] = m;
    }
    __syncthreads();
    #pragma unroll
    for (int mt = 0; mt < 4; mt++)
        #pragma unroll
        for (int i = 0; i < 2; i++){
            float mm = rmax[mt*16 + g + i*8];
            float s = 0.f;
            #pragma unroll
            for (int nt8 = 0; nt8 < 4; nt8++){
                float e0 = __expf(acc[mt][nt8][2*i]   - mm);
                float e1 = __expf(acc[mt][nt8][2*i+1] - mm);
                acc[mt][nt8][2*i] = e0; acc[mt][nt8][2*i+1] = e1;
                s += e0 + e1;
            }
            s += __shfl_xor_sync(~0u, s, 1);
            s += __shfl_xor_sync(~0u, s, 2);
            if (t4 == 0) red[(mt*16 + g + i*8)*8 + wid] = s;
        }
    __syncthreads();
    if (t < 64){
        float s = red[t*8];
        #pragma unroll
        for (int j = 1; j < 8; j++) s += red[t*8+j];
        rsum[t] = 1.f/s;
    }
    __syncthreads();
    #pragma unroll
    for (int mt = 0; mt < 4; mt++)
        #pragma unroll
        for (int i = 0; i < 2; i++){
            int row = mt*16 + g + i*8;
            float inv = rsum[row];
            __nv_bfloat16* dst = g_attn + (size_t)(b*NQ + qt*64 + row)*2048 + h*NK + wid*32;
            #pragma unroll
            for (int nt8 = 0; nt8 < 4; nt8++)
                *(u32*)(dst + nt8*8 + t4*2) = bf2(acc[mt][nt8][2*i]*inv,
                                                  acc[mt][nt8][2*i+1]*inv);
        }
}

// ===================== K3: bf16 mma attn @ vprojT + residual ================
__global__ void __launch_bounds__(256, 2) k3_av(const float* __restrict__ hidden,
                                                const float* __restrict__ bo,
                                                float* __restrict__ out){
    extern __shared__ u32 smp[];
    int t = threadIdx.x, wid = t>>5, lane = t&31;
    int g = lane>>2, t4 = lane&3;
    int nt = blockIdx.x, qt = blockIdx.y, b = blockIdx.z;

    u32 aofs = (u32)((((lane&7) + ((lane>>3)&1)*8)*AROW + ((lane>>4)&1)*4)*4);
    u32 bofs = (u32)(((((lane>>4)&1)*8 + (lane&7))*AROW + ((lane>>3)&1)*4)*4);

    const __nv_bfloat16* Ag = g_attn   + (size_t)(b*NQ + qt*64)*2048;
    const __nv_bfloat16* Bg = g_vprojT + (size_t)(b*768 + nt*256)*2048;
    u32 sb = smem_u32(smp);

    float acc[4][4][4];
    #pragma unroll
    for (int mt = 0; mt < 4; mt++)
        #pragma unroll
        for (int nt8 = 0; nt8 < 4; nt8++)
            #pragma unroll
            for (int r = 0; r < 4; r++) acc[mt][nt8][r] = 0.f;

    stage_tile(t, sb, Ag, Bg, 0, 2048);
    stage_tile(t, sb + BUFU*4, Ag, Bg, 1, 2048);
    for (int kc = 0; kc < 64; kc++){
        asm volatile("cp.async.wait_group 1;" ::: "memory");
        __syncthreads();
        if (kc + 2 < 64)
            stage_tile(t, sb + (u32)(((kc+2)%3)*BUFU)*4, Ag, Bg, kc+2, 2048);
        else
            asm volatile("cp.async.commit_group;" ::: "memory");
        gemm_chunk(sb + (u32)((kc%3)*BUFU)*4, acc, wid, aofs, bofs);
    }

    #pragma unroll
    for (int mt = 0; mt < 4; mt++)
        #pragma unroll
        for (int i = 0; i < 2; i++){
            int row = qt*64 + mt*16 + g + i*8;
            const float* hb = hidden + (size_t)(b*NQ + row)*768;
            float*       ob = out    + (size_t)(b*NQ + row)*768;
            #pragma unroll
            for (int nt8 = 0; nt8 < 4; nt8++){
                int col = nt*256 + wid*32 + nt8*8 + t4*2;
                float2 hv = *(const float2*)(hb + col);
                float vx = acc[mt][nt8][2*i]   + hv.x;
                float vy = acc[mt][nt8][2*i+1] + hv.y;
                if ((col & 15) == 0) vx += bo[col >> 4];
                *(float2*)(ob + col) = make_float2(vx, vy);
            }
        }
}

// ===========================================================================
extern "C" void kernel_launch(void* const* d_in, const int* in_sizes, int n_in,
                              void* d_out, int out_size){
    const float* hidden = (const float*)d_in[0];
    const float* vision = (const float*)d_in[1];
    const float* lnw    = (const float*)d_in[2];
    const float* Wq     = (const float*)d_in[3];
    const float* bq     = (const float*)d_in[4];
    const float* Wkv    = (const float*)d_in[5];
    const float* bkv    = (const float*)d_in[6];
    const float* Wo     = (const float*)d_in[7];
    const float* bo     = (const float*)d_in[8];
    const float* daa    = (const float*)d_in[9];
    float* out = (float*)d_out;

    const int s2x = (16*768 + 16)*4;
    const int s1a = (384*18)*4;                       // 27648
    const int s1b = (11520 + 2*6144)*4;               // 95232
    const int s2b = (3*BUFU)*4 + (512 + 64 + 64)*4;   // 79360
    const int s3  = (3*BUFU)*4;                        // 76800
    cudaFuncSetAttribute(k2x_xfeat, cudaFuncAttributeMaxDynamicSharedMemorySize, s2x);
    cudaFuncSetAttribute(k1a_kv,    cudaFuncAttributeMaxDynamicSharedMemorySize, s1a);
    cudaFuncSetAttribute(k1b_vproj, cudaFuncAttributeMaxDynamicSharedMemorySize, s1b);
    cudaFuncSetAttribute(k2b_logits,cudaFuncAttributeMaxDynamicSharedMemorySize, s2b);
    cudaFuncSetAttribute(k3_av,     cudaFuncAttributeMaxDynamicSharedMemorySize, s3);

    k0a_prep  <<<64, 256>>>(Wq, Wo, daa);                      // 0
    k0b_prep  <<<64, 256>>>(Wkv);                              // 1
    k2x_xfeat <<<dim3(NQ/16, BB), 256, s2x>>>(hidden, lnw);    // 2
    k1a_kv    <<<dim3(NK/16, 6, BB), 256, s1a>>>(vision, bkv); // 3 (profiled)
    k1b_vproj <<<dim3(3, HH, BB), 256, s1b>>>();               // 4
    k2m_M     <<<dim3(NK/32, HH, BB), 256>>>(bq);              // 5
    k2b_logits<<<dim3(NQ/64, HH, BB), 256, s2b>>>();           // 6
    k3_av     <<<dim3(3, NQ/64, BB), 256, s3>>>(hidden, bo, out); // 7
}

// round 14
// speedup vs baseline: 1.0710x; 1.0710x over previous
#include <cuda_runtime.h>
#include <cuda_bf16.h>
#include <math.h>
#include <stdint.h>

#define BB 8
#define NQ 1024
#define NK 256
#define HH 8
#define DF 528
#define DFP 576
#define DX 544

typedef unsigned long long u64;
typedef unsigned int u32;

__constant__ int c_cg[11]    = {0,1,1,1,2,2,2,3,3,3,3};
__constant__ int c_comps[11] = {0,2,3,4,8,9,10,14,11,12,13};
__constant__ int c_grade[16] = {0,1,1,1,1,2,2,2,2,2,2,3,3,3,3,4};

__device__ float g_WqT [5*48*384];
__device__ float g_WkvT[5*48*768];
__device__ float g_WoT [5*384*48];
__device__ float g_sp  [8];
__device__ __nv_bfloat16 g_xfeat [(size_t)BB*NQ*DX];
__device__ __nv_bfloat16 g_M     [(size_t)BB*HH*NK*DX];
__device__ float         g_kfeatT[(size_t)BB*HH*NK*DFP];
__device__ float         g_vtmp  [(size_t)BB*HH*16*12288];
__device__ __nv_bfloat16 g_vprojT[(size_t)BB*768*2048];
__device__ __nv_bfloat16 g_attn  [(size_t)BB*NQ*2048];

__device__ __forceinline__ u64 pk2(float lo, float hi){
    u64 u; asm("mov.b64 %0,{%1,%2};" : "=l"(u) : "f"(lo), "f"(hi)); return u;
}
__device__ __forceinline__ void upk2(u64 u, float& lo, float& hi){
    asm("mov.b64 {%0,%1},%2;" : "=f"(lo), "=f"(hi) : "l"(u));
}
__device__ __forceinline__ u64 f2fma(u64 a, u64 b, u64 c){
    u64 d; asm("fma.rn.f32x2 %0,%1,%2,%3;" : "=l"(d) : "l"(a), "l"(b), "l"(c)); return d;
}
__device__ __forceinline__ u32 bf2(float lo, float hi){
    u32 r; asm("cvt.rn.bf16x2.f32 %0,%1,%2;" : "=r"(r) : "f"(hi), "f"(lo)); return r;
}
__device__ __forceinline__ u32 smem_u32(const void* p){
    u32 a; asm("{ .reg .u64 t; cvta.to.shared.u64 t, %1; cvt.u32.u64 %0, t; }" : "=r"(a) : "l"(p));
    return a;
}
__device__ __forceinline__ void mma16816(float* d, const u32* a, const u32* b){
    asm volatile("mma.sync.aligned.m16n8k16.row.col.f32.bf16.bf16.f32 "
        "{%0,%1,%2,%3},{%4,%5,%6,%7},{%8,%9},{%0,%1,%2,%3};"
        : "+f"(d[0]), "+f"(d[1]), "+f"(d[2]), "+f"(d[3])
        : "r"(a[0]), "r"(a[1]), "r"(a[2]), "r"(a[3]), "r"(b[0]), "r"(b[1]));
}
__device__ __forceinline__ void ldsm4(u32& r0, u32& r1, u32& r2, u32& r3, u32 addr){
    asm volatile("ldmatrix.sync.aligned.m8n8.x4.shared.b16 {%0,%1,%2,%3},[%4];"
        : "=r"(r0), "=r"(r1), "=r"(r2), "=r"(r3) : "r"(addr));
}
__device__ __forceinline__ void cp16(u32 sdst, const void* gsrc){
    asm volatile("cp.async.cg.shared.global [%0], [%1], 16;" :: "r"(sdst), "l"(gsrc));
}

// ============ K0a: WqT + WoT transposes + softplus ==========================
__global__ void k0a_prep(const float* __restrict__ Wq, const float* __restrict__ Wo,
                         const float* __restrict__ daa){
    int stride = gridDim.x * blockDim.x;
    int gid = blockIdx.x * blockDim.x + threadIdx.x;
    for (int idx = gid; idx < 5*384*48; idx += stride){
        int g = idx/(384*48), rem = idx%(384*48), o = rem/48, i = rem%48;
        g_WqT[(g*48+i)*384+o] = Wq[idx];
    }
    for (int idx = gid; idx < 5*48*384; idx += stride){
        int g = idx/(48*384), rem = idx%(48*384), o = rem/384, i = rem%384;
        g_WoT[(g*384+i)*48+o] = Wo[idx];
    }
    if (gid < 8){
        float x = daa[gid];
        g_sp[gid] = (x > 20.f) ? x : log1pf(expf(x));
    }
}

// ============ K0b: WkvT transpose ===========================================
__global__ void k0b_prep(const float* __restrict__ Wkv){
    int stride = gridDim.x * blockDim.x;
    int gid = blockIdx.x * blockDim.x + threadIdx.x;
    for (int idx = gid; idx < 5*768*48; idx += stride){
        int g = idx/(768*48), rem = idx%(768*48), o = rem/48, i = rem%48;
        g_WkvT[(g*48+i)*768+o] = Wkv[idx];
    }
}

// ============ K2x: rmsnorm + reorder -> xfeat [row][544] (bf16) =============
__global__ void __launch_bounds__(256) k2x_xfeat(const float* __restrict__ hidden,
                                                 const float* __restrict__ lnw){
    extern __shared__ float sx[];
    float* rows = sx;               // 16*768
    float* rsq  = sx + 16*768;      // 16
    int b = blockIdx.y, q0 = blockIdx.x*16, t = threadIdx.x;
    const float* hrow = hidden + (size_t)(b*NQ+q0)*768;
    for (int idx = t; idx < 16*768; idx += 256) rows[idx] = hrow[idx];
    __syncthreads();
    { int r = t>>4, sub = t&15; float s = 0.f;
      for (int e = sub; e < 768; e += 16){ float v = rows[r*768+e]; s += v*v; }
      s += __shfl_xor_sync(~0u, s, 1);
      s += __shfl_xor_sync(~0u, s, 2);
      s += __shfl_xor_sync(~0u, s, 4);
      s += __shfl_xor_sync(~0u, s, 8);
      if (sub == 0) rsq[r] = rsqrtf(s*(1.f/48.f) + 1e-6f);
    }
    __syncthreads();
    __nv_bfloat16* dst = g_xfeat + (size_t)(b*NQ+q0)*DX;
    for (int idx = t; idx < 16*DX; idx += 256){
        int r = idx/DX, d = idx - r*DX;
        float val;
        if (d < DF){
            int js = d/48, in = d - js*48;
            val = rows[r*768 + in*16 + c_comps[js]] * rsq[r] * lnw[in];
        } else val = (d == DF) ? 1.f : 0.f;
        dst[idx] = __float2bfloat16(val);
    }
}

// ========== K1a: kv projection (R12 form, 2 CTA/SM); grid (ktile, s, b) =====
__global__ void __launch_bounds__(256, 2) k1a_kv(const float* __restrict__ vision,
                                                 const float* __restrict__ bkv){
    extern __shared__ float sm1[];
    float* xT = sm1;            // [(c*48+in)][key16] pad 18
    int b = blockIdx.z, s = blockIdx.y, k0 = blockIdx.x*16, t = threadIdx.x;

    for (int idx = t; idx < 16*768; idx += 256){
        int key = idx/768, e = idx - key*768, in = e>>4, c = e&15;
        xT[(c*48+in)*18 + key] = vision[((size_t)(b*NK + k0 + key))*768 + e];
    }
    __syncthreads();

    const float INVS = 0.051031036307982884f;  // 1/sqrt(384)
    const int GR[16] = {0,1,1,1,1,2,2,2,2,2,2,3,3,3,3,4};

    int o = t + 256*s;
    float bias = bkv[o];
    const float* wb = g_WkvT + o;
    for (int kt = 0; kt < 4; kt++){
        u64 acc[2][16];
        #pragma unroll
        for (int kp = 0; kp < 2; kp++){
            acc[kp][0] = pk2(bias, bias);
            #pragma unroll
            for (int c = 1; c < 16; c++) acc[kp][c] = 0ull;
        }
        #pragma unroll 4
        for (int in = 0; in < 48; in++){
            float w0 = wb[(0*48+in)*768], w1 = wb[(1*48+in)*768];
            float w2 = wb[(2*48+in)*768], w3 = wb[(3*48+in)*768];
            float w4 = wb[(4*48+in)*768];
            u64 wv[5] = {pk2(w0,w0), pk2(w1,w1), pk2(w2,w2), pk2(w3,w3), pk2(w4,w4)};
            #pragma unroll
            for (int c = 0; c < 16; c++){
                const float* xp = xT + (c*48+in)*18 + kt*4;
                acc[0][c] = f2fma(*(const u64*)(xp    ), wv[GR[c]], acc[0][c]);
                acc[1][c] = f2fma(*(const u64*)(xp + 2), wv[GR[c]], acc[1][c]);
            }
        }
        if (o < 384){
            int h = o/48, i = o - h*48;
            float sp = g_sp[h], spc = sp*(2.f/48.f);
            size_t rb = (size_t)((b*HH+h)*NK + k0 + kt*4)*DFP;
            const int IC[8] = {0,2,3,4,8,9,10,14};
            #pragma unroll
            for (int js = 0; js < 8; js++)
                #pragma unroll
                for (int kp = 0; kp < 2; kp++){
                    float lo, hi; upk2(acc[kp][IC[js]], lo, hi);
                    g_kfeatT[rb + (size_t)(2*kp  )*DFP + js*48+i] = lo*INVS;
                    g_kfeatT[rb + (size_t)(2*kp+1)*DFP + js*48+i] = hi*INVS;
                }
            const int PC[3] = {11,12,13};
            #pragma unroll
            for (int jp = 0; jp < 3; jp++)
                #pragma unroll
                for (int kp = 0; kp < 2; kp++){
                    float lo, hi; upk2(acc[kp][PC[jp]], lo, hi);
                    g_kfeatT[rb + (size_t)(2*kp  )*DFP + 384+jp*48+i] = lo*spc;
                    g_kfeatT[rb + (size_t)(2*kp+1)*DFP + 384+jp*48+i] = hi*spc;
                }
        } else {
            int vc = o - 384, h = vc/48, i = vc - h*48;
            float* vb = g_vtmp + ((size_t)((b*HH+h)*16 + (k0>>4)))*12288 + i*256 + kt*4;
            #pragma unroll
            for (int c = 0; c < 16; c++){
                *(u64*)&vb[c*16]     = acc[0][c];
                *(u64*)&vb[c*16 + 2] = acc[1][c];
            }
        }
    }
}

// ========== K1b: vprojT via cp.async double-buffered subtiles ===============
__device__ __forceinline__ void k1b_stage(int t, u32 sb, const float* Vg, int s){
    const float* src = Vg + (size_t)(s>>1)*12288 + (s&1)*8;
    u32 dst = sb + (u32)((s&1)*6144)*4;
    #pragma unroll
    for (int it = 0; it < 6; it++){
        int idx = t + 256*it;            // 1536 chunks of 16B
        int row = idx>>1, part = idx&1;
        cp16(dst + (u32)(row*8 + part*4)*4, src + row*16 + part*4);
    }
    asm volatile("cp.async.commit_group;" ::: "memory");
}

__global__ void __launch_bounds__(256) k1b_vproj(){
    extern __shared__ float sm2[];
    float* w_s = sm2;             // 11520
    float* v_s = sm2 + 11520;     // 2 * 6144
    int sl = blockIdx.x, h = blockIdx.y, b = blockIdx.z, t = threadIdx.x;

    for (int idx = t; idx < 11520; idx += 256){
        int g = idx/2304, r = idx - g*2304;
        w_s[idx] = g_WoT[(g*384 + h*48)*48 + r];
    }
    int j = sl*256 + t;
    int o48 = j % 48, c = j / 48;
    int g = c_grade[c];
    const float* Vg = g_vtmp + (size_t)((b*HH+h)*16)*12288;
    u32 sb = smem_u32(v_s);
    const float* wp = w_s + g*2304 + o48;

    k1b_stage(t, sb, Vg, 0);
    for (int s = 0; s < 32; s++){
        if (s + 1 < 32){
            k1b_stage(t, sb, Vg, s+1);
            asm volatile("cp.async.wait_group 1;" ::: "memory");
        } else {
            asm volatile("cp.async.wait_group 0;" ::: "memory");
        }
        __syncthreads();
        const float* vp0 = v_s + (s&1)*6144 + c*8;
        u64 acc[4] = {0ull, 0ull, 0ull, 0ull};
        #pragma unroll 8
        for (int i = 0; i < 48; i++){
            float w = wp[i*48];
            u64 w2 = pk2(w, w);
            const float* vp = vp0 + i*128;
            acc[0] = f2fma(*(const u64*)(vp    ), w2, acc[0]);
            acc[1] = f2fma(*(const u64*)(vp + 2), w2, acc[1]);
            acc[2] = f2fma(*(const u64*)(vp + 4), w2, acc[2]);
            acc[3] = f2fma(*(const u64*)(vp + 6), w2, acc[3]);
        }
        u32 r4[4];
        #pragma unroll
        for (int kp = 0; kp < 4; kp++){
            float lo, hi; upk2(acc[kp], lo, hi);
            r4[kp] = bf2(lo, hi);
        }
        __nv_bfloat16* dst = g_vprojT + (size_t)(b*768 + o48*16 + c)*2048
                           + h*256 + (s>>1)*16 + (s&1)*8;
        *(uint4*)dst = *(const uint4*)r4;
        __syncthreads();
    }
}

// ======= K2m: M[b,h][k][544] (bf16) — 512 CTAs, 32 keys each ================
__global__ void __launch_bounds__(256) k2m_M(const float* __restrict__ bq){
    __shared__ float kfT[48*34];   // [j][key32] pad 34
    __shared__ float ws [48*49];   // [j][c] pad 49
    __shared__ float mT [48*34];   // [c][key32] pad 34
    __shared__ float kb32[32];
    __shared__ float ss32[32];
    int kt0 = blockIdx.x*32, h = blockIdx.y, b = blockIdx.z, t = threadIdx.x;
    size_t kbase = (size_t)((b*HH+h)*NK) + kt0;
    if (t < 32) ss32[t] = 0.f;

    for (int js = 0; js < 11; js++){
        int g = c_cg[js];
        __syncthreads();
        #pragma unroll
        for (int r = 0; r < 6; r++){
            int idx = t + 256*r;                // 48*32 = 1536
            if (idx < 1536){
                int k = idx/48, j = idx - k*48;
                kfT[j*34 + k] = g_kfeatT[(kbase + k)*DFP + js*48 + j];
            }
        }
        #pragma unroll
        for (int r = 0; r < 9; r++){
            int idx = t + 256*r;                // 2304
            if (idx < 2304){
                int c = idx/48, j = idx - c*48;
                ws[j*49 + c] = g_WqT[(g*48+c)*384 + h*48 + j];
            }
        }
        __syncthreads();
        if (js == 0 && t < 32){
            float s = 0.f;
            #pragma unroll 8
            for (int j = 0; j < 48; j++) s += bq[h*48+j]*kfT[j*34 + t];
            kb32[t] = s;
        }
        if (js >= 8 && t < 32){
            float s = 0.f;
            #pragma unroll 8
            for (int j = 0; j < 48; j++){ float v = kfT[j*34 + t]; s += v*v; }
            ss32[t] += s;
        }
        #pragma unroll
        for (int r = 0; r < 3; r++){
            int o = t + 256*r;                  // 768 = 48c * 16 keypairs
            int c = o >> 4, kp = o & 15;
            u64 acc = 0ull;
            #pragma unroll 8
            for (int j = 0; j < 48; j++){
                float w = ws[j*49 + c];
                acc = f2fma(*(const u64*)&kfT[j*34 + 2*kp], pk2(w, w), acc);
            }
            *(u64*)&mT[c*34 + 2*kp] = acc;
        }
        __syncthreads();
        #pragma unroll
        for (int r = 0; r < 6; r++){
            int idx = t + 256*r;
            if (idx < 1536){
                int k = idx/48, c = idx - k*48;
                g_M[(kbase + k)*DX + js*48 + c] = __float2bfloat16(mT[c*34 + k]);
            }
        }
    }
    __syncthreads();
    float sp = g_sp[h];
    #pragma unroll
    for (int r = 0; r < 2; r++){
        int idx = t + 256*r;                    // 32*16 = 512
        int k = idx >> 4, cc = idx & 15;
        float v = (cc == 0) ? (kb32[k] - (12.f/sp)*ss32[k]) : 0.f;
        g_M[(kbase + k)*DX + DF + cc] = __float2bfloat16(v);
    }
}

// ============ bf16 GEMM core: 64 rows x 256 cols, ldmatrix + mma16816 =======
#define AROW 20
#define BOFF 1280
#define BUFU 6400

__device__ __forceinline__ void gemm_chunk(u32 base, float acc[4][4][4],
                                           int wid, u32 aofs, u32 bofs){
    #pragma unroll
    for (int k16 = 0; k16 < 2; k16++){
        int ko = k16*8;
        u32 au[4][4];
        #pragma unroll
        for (int mt = 0; mt < 4; mt++)
            ldsm4(au[mt][0], au[mt][1], au[mt][2], au[mt][3],
                  base + (u32)(mt*16*AROW + ko)*4 + aofs);
        u32 bu[4][2];
        ldsm4(bu[0][0], bu[0][1], bu[1][0], bu[1][1],
              base + (u32)(BOFF + wid*32*AROW + ko)*4 + bofs);
        ldsm4(bu[2][0], bu[2][1], bu[3][0], bu[3][1],
              base + (u32)(BOFF + (wid*32+16)*AROW + ko)*4 + bofs);
        #pragma unroll
        for (int mt = 0; mt < 4; mt++)
            #pragma unroll
            for (int nt8 = 0; nt8 < 4; nt8++)
                mma16816(acc[mt][nt8], au[mt], bu[nt8]);
    }
}

__device__ __forceinline__ void stage_tile(int t, u32 sb, const __nv_bfloat16* Ag,
                                           const __nv_bfloat16* Bg, int kc, int stride){
    { int row = t>>2, seg = t&3;
      cp16(sb + (u32)(row*AROW + seg*4)*4, Ag + (size_t)row*stride + kc*32 + seg*8); }
    #pragma unroll
    for (int it = 0; it < 4; it++){
        int i = t + 256*it, row = i>>2, seg = i&3;
        cp16(sb + (u32)(BOFF + row*AROW + seg*4)*4, Bg + (size_t)row*stride + kc*32 + seg*8);
    }
    asm volatile("cp.async.commit_group;" ::: "memory");
}

// ===================== K2b: bf16 mma logits + softmax ======================
__global__ void __launch_bounds__(256, 2) k2b_logits(){
    extern __shared__ u32 smp[];
    float* red  = (float*)(smp + 3*BUFU);   // 512
    float* rmax = red + 512;
    float* rsum = rmax + 64;
    int t = threadIdx.x, wid = t>>5, lane = t&31;
    int g = lane>>2, t4 = lane&3;
    int qt = blockIdx.x, h = blockIdx.y, b = blockIdx.z;

    u32 aofs = (u32)((((lane&7) + ((lane>>3)&1)*8)*AROW + ((lane>>4)&1)*4)*4);
    u32 bofs = (u32)(((((lane>>4)&1)*8 + (lane&7))*AROW + ((lane>>3)&1)*4)*4);

    const __nv_bfloat16* Ag = g_xfeat + (size_t)(b*NQ + qt*64)*DX;
    const __nv_bfloat16* Bg = g_M     + (size_t)((b*HH+h)*NK)*DX;
    u32 sb = smem_u32(smp);

    float acc[4][4][4];
    #pragma unroll
    for (int mt = 0; mt < 4; mt++)
        #pragma unroll
        for (int nt8 = 0; nt8 < 4; nt8++)
            #pragma unroll
            for (int r = 0; r < 4; r++) acc[mt][nt8][r] = 0.f;

    stage_tile(t, sb, Ag, Bg, 0, DX);
    stage_tile(t, sb + BUFU*4, Ag, Bg, 1, DX);
    for (int kc = 0; kc < 17; kc++){
        asm volatile("cp.async.wait_group 1;" ::: "memory");
        __syncthreads();
        if (kc + 2 < 17)
            stage_tile(t, sb + (u32)(((kc+2)%3)*BUFU)*4, Ag, Bg, kc+2, DX);
        else
            asm volatile("cp.async.commit_group;" ::: "memory");
        gemm_chunk(sb + (u32)((kc%3)*BUFU)*4, acc, wid, aofs, bofs);
    }

    __syncthreads();
    #pragma unroll
    for (int mt = 0; mt < 4; mt++)
        #pragma unroll
        for (int i = 0; i < 2; i++){
            float m = -1e30f;
            #pragma unroll
            for (int nt8 = 0; nt8 < 4; nt8++)
                m = fmaxf(m, fmaxf(acc[mt][nt8][2*i], acc[mt][nt8][2*i+1]));
            m = fmaxf(m, __shfl_xor_sync(~0u, m, 1));
            m = fmaxf(m, __shfl_xor_sync(~0u, m, 2));
            if (t4 == 0) red[(mt*16 + g + i*8)*8 + wid] = m;
        }
    __syncthreads();
    if (t < 64){
        float m = red[t*8];
        #pragma unroll
        for (int j = 1; j < 8; j++) m = fmaxf(m, red[t*8+j]);
        rmax[t] = m;
    }
    __syncthreads();
    #pragma unroll
    for (int mt = 0; mt < 4; mt++)
        #pragma unroll
        for (int i = 0; i < 2; i++){
            float mm = rmax[mt*16 + g + i*8];
            float s = 0.f;
            #pragma unroll
            for (int nt8 = 0; nt8 < 4; nt8++){
                float e0 = __expf(acc[mt][nt8][2*i]   - mm);
                float e1 = __expf(acc[mt][nt8][2*i+1] - mm);
                acc[mt][nt8][2*i] = e0; acc[mt][nt8][2*i+1] = e1;
                s += e0 + e1;
            }
            s += __shfl_xor_sync(~0u, s, 1);
            s += __shfl_xor_sync(~0u, s, 2);
            if (t4 == 0) red[(mt*16 + g + i*8)*8 + wid] = s;
        }
    __syncthreads();
    if (t < 64){
        float s = red[t*8];
        #pragma unroll
        for (int j = 1; j < 8; j++) s += red[t*8+j];
        rsum[t] = 1.f/s;
    }
    __syncthreads();
    #pragma unroll
    for (int mt = 0; mt < 4; mt++)
        #pragma unroll
        for (int i = 0; i < 2; i++){
            int row = mt*16 + g + i*8;
            float inv = rsum[row];
            __nv_bfloat16* dst = g_attn + (size_t)(b*NQ + qt*64 + row)*2048 + h*NK + wid*32;
            #pragma unroll
            for (int nt8 = 0; nt8 < 4; nt8++)
                *(u32*)(dst + nt8*8 + t4*2) = bf2(acc[mt][nt8][2*i]*inv,
                                                  acc[mt][nt8][2*i+1]*inv);
        }
}

// ===================== K3: bf16 mma attn @ vprojT + residual ================
__global__ void __launch_bounds__(256, 2) k3_av(const float* __restrict__ hidden,
                                                const float* __restrict__ bo,
                                                float* __restrict__ out){
    extern __shared__ u32 smp[];
    int t = threadIdx.x, wid = t>>5, lane = t&31;
    int g = lane>>2, t4 = lane&3;
    int nt = blockIdx.x, qt = blockIdx.y, b = blockIdx.z;

    u32 aofs = (u32)((((lane&7) + ((lane>>3)&1)*8)*AROW + ((lane>>4)&1)*4)*4);
    u32 bofs = (u32)(((((lane>>4)&1)*8 + (lane&7))*AROW + ((lane>>3)&1)*4)*4);

    const __nv_bfloat16* Ag = g_attn   + (size_t)(b*NQ + qt*64)*2048;
    const __nv_bfloat16* Bg = g_vprojT + (size_t)(b*768 + nt*256)*2048;
    u32 sb = smem_u32(smp);

    float acc[4][4][4];
    #pragma unroll
    for (int mt = 0; mt < 4; mt++)
        #pragma unroll
        for (int nt8 = 0; nt8 < 4; nt8++)
            #pragma unroll
            for (int r = 0; r < 4; r++) acc[mt][nt8][r] = 0.f;

    stage_tile(t, sb, Ag, Bg, 0, 2048);
    stage_tile(t, sb + BUFU*4, Ag, Bg, 1, 2048);
    for (int kc = 0; kc < 64; kc++){
        asm volatile("cp.async.wait_group 1;" ::: "memory");
        __syncthreads();
        if (kc + 2 < 64)
            stage_tile(t, sb + (u32)(((kc+2)%3)*BUFU)*4, Ag, Bg, kc+2, 2048);
        else
            asm volatile("cp.async.commit_group;" ::: "memory");
        gemm_chunk(sb + (u32)((kc%3)*BUFU)*4, acc, wid, aofs, bofs);
    }

    #pragma unroll
    for (int mt = 0; mt < 4; mt++)
        #pragma unroll
        for (int i = 0; i < 2; i++){
            int row = qt*64 + mt*16 + g + i*8;
            const float* hb = hidden + (size_t)(b*NQ + row)*768;
            float*       ob = out    + (size_t)(b*NQ + row)*768;
            #pragma unroll
            for (int nt8 = 0; nt8 < 4; nt8++){
                int col = nt*256 + wid*32 + nt8*8 + t4*2;
                float2 hv = *(const float2*)(hb + col);
                float vx = acc[mt][nt8][2*i]   + hv.x;
                float vy = acc[mt][nt8][2*i+1] + hv.y;
                if ((col & 15) == 0) vx += bo[col >> 4];
                *(float2*)(ob + col) = make_float2(vx, vy);
            }
        }
}

// ===========================================================================
extern "C" void kernel_launch(void* const* d_in, const int* in_sizes, int n_in,
                              void* d_out, int out_size){
    const float* hidden = (const float*)d_in[0];
    const float* vision = (const float*)d_in[1];
    const float* lnw    = (const float*)d_in[2];
    const float* Wq     = (const float*)d_in[3];
    const float* bq     = (const float*)d_in[4];
    const float* Wkv    = (const float*)d_in[5];
    const float* bkv    = (const float*)d_in[6];
    const float* Wo     = (const float*)d_in[7];
    const float* bo     = (const float*)d_in[8];
    const float* daa    = (const float*)d_in[9];
    float* out = (float*)d_out;

    const int s2x = (16*768 + 16)*4;
    const int s1a = (768*18)*4;                       // 55296
    const int s1b = (11520 + 2*6144)*4;               // 95232
    const int s2b = (3*BUFU)*4 + (512 + 64 + 64)*4;   // 79360
    const int s3  = (3*BUFU)*4;                        // 76800
    cudaFuncSetAttribute(k2x_xfeat, cudaFuncAttributeMaxDynamicSharedMemorySize, s2x);
    cudaFuncSetAttribute(k1a_kv,    cudaFuncAttributeMaxDynamicSharedMemorySize, s1a);
    cudaFuncSetAttribute(k1b_vproj, cudaFuncAttributeMaxDynamicSharedMemorySize, s1b);
    cudaFuncSetAttribute(k2b_logits,cudaFuncAttributeMaxDynamicSharedMemorySize, s2b);
    cudaFuncSetAttribute(k3_av,     cudaFuncAttributeMaxDynamicSharedMemorySize, s3);

    k0a_prep  <<<64, 256>>>(Wq, Wo, daa);                      // 0
    k0b_prep  <<<64, 256>>>(Wkv);                              // 1
    k2x_xfeat <<<dim3(NQ/16, BB), 256, s2x>>>(hidden, lnw);    // 2
    k1a_kv    <<<dim3(NK/16, 3, BB), 256, s1a>>>(vision, bkv); // 3 (profiled)
    k1b_vproj <<<dim3(3, HH, BB), 256, s1b>>>();               // 4
    k2m_M     <<<dim3(NK/32, HH, BB), 256>>>(bq);              // 5
    k2b_logits<<<dim3(NQ/64, HH, BB), 256, s2b>>>();           // 6
    k3_av     <<<dim3(3, NQ/64, BB), 256, s3>>>(hidden, bo, out); // 7
}

// round 15
// speedup vs baseline: 1.6917x; 1.5795x over previous
#include <cuda_runtime.h>
#include <cuda_bf16.h>
#include <math.h>
#include <stdint.h>

#define BB 8
#define NQ 1024
#define NK 256
#define HH 8
#define DF 528
#define DFP 576
#define DX 544

typedef unsigned long long u64;
typedef unsigned int u32;

__constant__ int c_cg[11]    = {0,1,1,1,2,2,2,3,3,3,3};
__constant__ int c_comps[11] = {0,2,3,4,8,9,10,14,11,12,13};
__constant__ int c_grade[16] = {0,1,1,1,1,2,2,2,2,2,2,3,3,3,3,4};

__device__ float g_WqT [5*48*384];
__device__ float g_WkvT[5*48*768];
__device__ float g_WoT [5*384*48];
__device__ float g_sp  [8];
__device__ __nv_bfloat16 g_xfeat [(size_t)BB*NQ*DX];
__device__ __nv_bfloat16 g_M     [(size_t)BB*HH*NK*DX];
__device__ float         g_kfeatT[(size_t)BB*HH*NK*DFP];
__device__ float         g_vtmp  [(size_t)BB*HH*16*12288];
__device__ __nv_bfloat16 g_vprojT[(size_t)BB*768*2048];
__device__ __nv_bfloat16 g_attn  [(size_t)BB*NQ*2048];

__device__ __forceinline__ u64 pk2(float lo, float hi){
    u64 u; asm("mov.b64 %0,{%1,%2};" : "=l"(u) : "f"(lo), "f"(hi)); return u;
}
__device__ __forceinline__ void upk2(u64 u, float& lo, float& hi){
    asm("mov.b64 {%0,%1},%2;" : "=f"(lo), "=f"(hi) : "l"(u));
}
__device__ __forceinline__ u64 f2fma(u64 a, u64 b, u64 c){
    u64 d; asm("fma.rn.f32x2 %0,%1,%2,%3;" : "=l"(d) : "l"(a), "l"(b), "l"(c)); return d;
}
__device__ __forceinline__ u32 bf2(float lo, float hi){
    u32 r; asm("cvt.rn.bf16x2.f32 %0,%1,%2;" : "=r"(r) : "f"(hi), "f"(lo)); return r;
}
__device__ __forceinline__ u32 smem_u32(const void* p){
    u32 a; asm("{ .reg .u64 t; cvta.to.shared.u64 t, %1; cvt.u32.u64 %0, t; }" : "=r"(a) : "l"(p));
    return a;
}
__device__ __forceinline__ void mma16816(float* d, const u32* a, const u32* b){
    asm volatile("mma.sync.aligned.m16n8k16.row.col.f32.bf16.bf16.f32 "
        "{%0,%1,%2,%3},{%4,%5,%6,%7},{%8,%9},{%0,%1,%2,%3};"
        : "+f"(d[0]), "+f"(d[1]), "+f"(d[2]), "+f"(d[3])
        : "r"(a[0]), "r"(a[1]), "r"(a[2]), "r"(a[3]), "r"(b[0]), "r"(b[1]));
}
__device__ __forceinline__ void ldsm4(u32& r0, u32& r1, u32& r2, u32& r3, u32 addr){
    asm volatile("ldmatrix.sync.aligned.m8n8.x4.shared.b16 {%0,%1,%2,%3},[%4];"
        : "=r"(r0), "=r"(r1), "=r"(r2), "=r"(r3) : "r"(addr));
}
__device__ __forceinline__ void cp16(u32 sdst, const void* gsrc){
    asm volatile("cp.async.cg.shared.global [%0], [%1], 16;" :: "r"(sdst), "l"(gsrc));
}

// ============ K0a: WqT + WoT transposes + softplus ==========================
__global__ void k0a_prep(const float* __restrict__ Wq, const float* __restrict__ Wo,
                         const float* __restrict__ daa){
    int stride = gridDim.x * blockDim.x;
    int gid = blockIdx.x * blockDim.x + threadIdx.x;
    for (int idx = gid; idx < 5*384*48; idx += stride){
        int g = idx/(384*48), rem = idx%(384*48), o = rem/48, i = rem%48;
        g_WqT[(g*48+i)*384+o] = Wq[idx];
    }
    for (int idx = gid; idx < 5*48*384; idx += stride){
        int g = idx/(48*384), rem = idx%(48*384), o = rem/384, i = rem%384;
        g_WoT[(g*384+i)*48+o] = Wo[idx];
    }
    if (gid < 8){
        float x = daa[gid];
        g_sp[gid] = (x > 20.f) ? x : log1pf(expf(x));
    }
}

// ============ K0b: WkvT transpose ===========================================
__global__ void k0b_prep(const float* __restrict__ Wkv){
    int stride = gridDim.x * blockDim.x;
    int gid = blockIdx.x * blockDim.x + threadIdx.x;
    for (int idx = gid; idx < 5*768*48; idx += stride){
        int g = idx/(768*48), rem = idx%(768*48), o = rem/48, i = rem%48;
        g_WkvT[(g*48+i)*768+o] = Wkv[idx];
    }
}

// ============ K2x: rmsnorm + reorder -> xfeat [row][544] (bf16) =============
__global__ void __launch_bounds__(256) k2x_xfeat(const float* __restrict__ hidden,
                                                 const float* __restrict__ lnw){
    extern __shared__ float sx[];
    float* rows = sx;               // 16*768
    float* rsq  = sx + 16*768;      // 16
    int b = blockIdx.y, q0 = blockIdx.x*16, t = threadIdx.x;
    const float* hrow = hidden + (size_t)(b*NQ+q0)*768;
    for (int idx = t; idx < 16*768; idx += 256) rows[idx] = hrow[idx];
    __syncthreads();
    { int r = t>>4, sub = t&15; float s = 0.f;
      for (int e = sub; e < 768; e += 16){ float v = rows[r*768+e]; s += v*v; }
      s += __shfl_xor_sync(~0u, s, 1);
      s += __shfl_xor_sync(~0u, s, 2);
      s += __shfl_xor_sync(~0u, s, 4);
      s += __shfl_xor_sync(~0u, s, 8);
      if (sub == 0) rsq[r] = rsqrtf(s*(1.f/48.f) + 1e-6f);
    }
    __syncthreads();
    __nv_bfloat16* dst = g_xfeat + (size_t)(b*NQ+q0)*DX;
    for (int idx = t; idx < 16*DX; idx += 256){
        int r = idx/DX, d = idx - r*DX;
        float val;
        if (d < DF){
            int js = d/48, in = d - js*48;
            val = rows[r*768 + in*16 + c_comps[js]] * rsq[r] * lnw[in];
        } else val = (d == DF) ? 1.f : 0.f;
        dst[idx] = __float2bfloat16(val);
    }
}

// ========== K1a: kv projection; grid (ktile, s, b); LDS.128 x-loads =========
__global__ void __launch_bounds__(256) k1a_kv(const float* __restrict__ vision,
                                              const float* __restrict__ bkv){
    extern __shared__ float sm1[];
    float* xT = sm1;            // [(c*48+in)][key16] pad 20 (16B aligned rows)
    int b = blockIdx.z, s = blockIdx.y, k0 = blockIdx.x*16, t = threadIdx.x;

    for (int idx = t; idx < 16*768; idx += 256){
        int key = idx/768, e = idx - key*768, in = e>>4, c = e&15;
        xT[(c*48+in)*20 + key] = vision[((size_t)(b*NK + k0 + key))*768 + e];
    }
    __syncthreads();

    const float INVS = 0.051031036307982884f;  // 1/sqrt(384)
    const int GR[16] = {0,1,1,1,1,2,2,2,2,2,2,3,3,3,3,4};

    int o = t + 256*s;
    float bias = bkv[o];
    const float* wb = g_WkvT + o;
    for (int kt = 0; kt < 4; kt++){
        u64 acc[2][16];
        #pragma unroll
        for (int kp = 0; kp < 2; kp++){
            acc[kp][0] = pk2(bias, bias);
            #pragma unroll
            for (int c = 1; c < 16; c++) acc[kp][c] = 0ull;
        }
        #pragma unroll 4
        for (int in = 0; in < 48; in++){
            float w0 = wb[(0*48+in)*768], w1 = wb[(1*48+in)*768];
            float w2 = wb[(2*48+in)*768], w3 = wb[(3*48+in)*768];
            float w4 = wb[(4*48+in)*768];
            u64 wv[5] = {pk2(w0,w0), pk2(w1,w1), pk2(w2,w2), pk2(w3,w3), pk2(w4,w4)};
            #pragma unroll
            for (int c = 0; c < 16; c++){
                float4 xv = *(const float4*)(xT + (c*48+in)*20 + kt*4);
                acc[0][c] = f2fma(pk2(xv.x, xv.y), wv[GR[c]], acc[0][c]);
                acc[1][c] = f2fma(pk2(xv.z, xv.w), wv[GR[c]], acc[1][c]);
            }
        }
        if (o < 384){
            int h = o/48, i = o - h*48;
            float sp = g_sp[h], spc = sp*(2.f/48.f);
            size_t rb = (size_t)((b*HH+h)*NK + k0 + kt*4)*DFP;
            const int IC[8] = {0,2,3,4,8,9,10,14};
            #pragma unroll
            for (int js = 0; js < 8; js++)
                #pragma unroll
                for (int kp = 0; kp < 2; kp++){
                    float lo, hi; upk2(acc[kp][IC[js]], lo, hi);
                    g_kfeatT[rb + (size_t)(2*kp  )*DFP + js*48+i] = lo*INVS;
                    g_kfeatT[rb + (size_t)(2*kp+1)*DFP + js*48+i] = hi*INVS;
                }
            const int PC[3] = {11,12,13};
            #pragma unroll
            for (int jp = 0; jp < 3; jp++)
                #pragma unroll
                for (int kp = 0; kp < 2; kp++){
                    float lo, hi; upk2(acc[kp][PC[jp]], lo, hi);
                    g_kfeatT[rb + (size_t)(2*kp  )*DFP + 384+jp*48+i] = lo*spc;
                    g_kfeatT[rb + (size_t)(2*kp+1)*DFP + 384+jp*48+i] = hi*spc;
                }
        } else {
            int vc = o - 384, h = vc/48, i = vc - h*48;
            float* vb = g_vtmp + ((size_t)((b*HH+h)*16 + (k0>>4)))*12288 + i*256 + kt*4;
            #pragma unroll
            for (int c = 0; c < 16; c++){
                *(u64*)&vb[c*16]     = acc[0][c];
                *(u64*)&vb[c*16 + 2] = acc[1][c];
            }
        }
    }
}

// ========== K1b: vprojT via cp.async pipelined subtiles =====================
__global__ void __launch_bounds__(256) k1b_vproj(){
    extern __shared__ float sm2[];
    float* w_s = sm2;             // 11520
    float* v_s = sm2 + 11520;     // 2 * 6144
    int sl = blockIdx.x, h = blockIdx.y, b = blockIdx.z, t = threadIdx.x;

    for (int idx = t; idx < 11520; idx += 256){
        int g = idx/2304, r = idx - g*2304;
        w_s[idx] = g_WoT[(g*384 + h*48)*48 + r];
    }
    int j = sl*256 + t;
    int o48 = j % 48, c = j / 48;
    int g = c_grade[c];
    const float* Vg = g_vtmp + (size_t)((b*HH+h)*16)*12288;
    u32 sb = smem_u32(v_s);
    const float* wp = w_s + g*2304 + o48;

    {   // stage s = 0
        const float* src = Vg;
        #pragma unroll
        for (int it = 0; it < 6; it++){
            int idx = t + 256*it;
            int row = idx>>1, part = idx&1;
            cp16(sb + (u32)(row*8 + part*4)*4, src + row*16 + part*4);
        }
        asm volatile("cp.async.commit_group;" ::: "memory");
    }

    for (int s = 0; s < 32; s++){
        asm volatile("cp.async.wait_group 0;" ::: "memory");
        __syncthreads();
        if (s + 1 < 32){
            const float* src = Vg + (size_t)((s+1)>>1)*12288 + ((s+1)&1)*8;
            int buf = (s+1)&1;
            #pragma unroll
            for (int it = 0; it < 6; it++){
                int idx = t + 256*it;
                int row = idx>>1, part = idx&1;
                cp16(sb + (u32)(buf*6144 + row*8 + part*4)*4, src + row*16 + part*4);
            }
            asm volatile("cp.async.commit_group;" ::: "memory");
        } else {
            asm volatile("cp.async.commit_group;" ::: "memory");
        }
        const float* vp0 = v_s + (s&1)*6144 + c*8;
        u64 acc[4] = {0ull, 0ull, 0ull, 0ull};
        #pragma unroll 8
        for (int i = 0; i < 48; i++){
            float w = wp[i*48];
            u64 w2 = pk2(w, w);
            const float* vp = vp0 + i*128;
            acc[0] = f2fma(*(const u64*)(vp    ), w2, acc[0]);
            acc[1] = f2fma(*(const u64*)(vp + 2), w2, acc[1]);
            acc[2] = f2fma(*(const u64*)(vp + 4), w2, acc[2]);
            acc[3] = f2fma(*(const u64*)(vp + 6), w2, acc[3]);
        }
        u32 r4[4];
        #pragma unroll
        for (int kp = 0; kp < 4; kp++){
            float lo, hi; upk2(acc[kp], lo, hi);
            r4[kp] = bf2(lo, hi);
        }
        __nv_bfloat16* dst = g_vprojT + (size_t)(b*768 + o48*16 + c)*2048
                           + h*256 + (s>>1)*16 + (s&1)*8;
        *(uint4*)dst = *(const uint4*)r4;
        __syncthreads();
    }
}

// ======= K2m: M[b,h][k][544] (bf16) — 512 CTAs, 32 keys each ================
__global__ void __launch_bounds__(256) k2m_M(const float* __restrict__ bq){
    __shared__ float kfT[48*34];   // [j][key32] pad 34
    __shared__ float ws [48*49];   // [j][c] pad 49
    __shared__ float mT [48*34];   // [c][key32] pad 34
    __shared__ float kb32[32];
    __shared__ float ss32[32];
    int kt0 = blockIdx.x*32, h = blockIdx.y, b = blockIdx.z, t = threadIdx.x;
    size_t kbase = (size_t)((b*HH+h)*NK) + kt0;
    if (t < 32) ss32[t] = 0.f;

    for (int js = 0; js < 11; js++){
        int g = c_cg[js];
        __syncthreads();
        #pragma unroll
        for (int r = 0; r < 6; r++){
            int idx = t + 256*r;
            if (idx < 1536){
                int k = idx/48, j = idx - k*48;
                kfT[j*34 + k] = g_kfeatT[(kbase + k)*DFP + js*48 + j];
            }
        }
        #pragma unroll
        for (int r = 0; r < 9; r++){
            int idx = t + 256*r;
            if (idx < 2304){
                int c = idx/48, j = idx - c*48;
                ws[j*49 + c] = g_WqT[(g*48+c)*384 + h*48 + j];
            }
        }
        __syncthreads();
        if (js == 0 && t < 32){
            float s = 0.f;
            #pragma unroll 8
            for (int j = 0; j < 48; j++) s += bq[h*48+j]*kfT[j*34 + t];
            kb32[t] = s;
        }
        if (js >= 8 && t < 32){
            float s = 0.f;
            #pragma unroll 8
            for (int j = 0; j < 48; j++){ float v = kfT[j*34 + t]; s += v*v; }
            ss32[t] += s;
        }
        #pragma unroll
        for (int r = 0; r < 3; r++){
            int o = t + 256*r;
            int c = o >> 4, kp = o & 15;
            u64 acc = 0ull;
            #pragma unroll 8
            for (int j = 0; j < 48; j++){
                float w = ws[j*49 + c];
                acc = f2fma(*(const u64*)&kfT[j*34 + 2*kp], pk2(w, w), acc);
            }
            *(u64*)&mT[c*34 + 2*kp] = acc;
        }
        __syncthreads();
        #pragma unroll
        for (int r = 0; r < 6; r++){
            int idx = t + 256*r;
            if (idx < 1536){
                int k = idx/48, c = idx - k*48;
                g_M[(kbase + k)*DX + js*48 + c] = __float2bfloat16(mT[c*34 + k]);
            }
        }
    }
    __syncthreads();
    float sp = g_sp[h];
    #pragma unroll
    for (int r = 0; r < 2; r++){
        int idx = t + 256*r;
        int k = idx >> 4, cc = idx & 15;
        float v = (cc == 0) ? (kb32[k] - (12.f/sp)*ss32[k]) : 0.f;
        g_M[(kbase + k)*DX + DF + cc] = __float2bfloat16(v);
    }
}

// ============ bf16 GEMM core: 64 rows x 256 cols, ldmatrix + mma16816 =======
#define AROW 20
#define BOFF 1280
#define BUFU 6400

__device__ __forceinline__ void gemm_chunk(u32 base, float acc[4][4][4],
                                           int wid, u32 aofs, u32 bofs){
    #pragma unroll
    for (int k16 = 0; k16 < 2; k16++){
        int ko = k16*8;
        u32 au[4][4];
        #pragma unroll
        for (int mt = 0; mt < 4; mt++)
            ldsm4(au[mt][0], au[mt][1], au[mt][2], au[mt][3],
                  base + (u32)(mt*16*AROW + ko)*4 + aofs);
        u32 bu[4][2];
        ldsm4(bu[0][0], bu[0][1], bu[1][0], bu[1][1],
              base + (u32)(BOFF + wid*32*AROW + ko)*4 + bofs);
        ldsm4(bu[2][0], bu[2][1], bu[3][0], bu[3][1],
              base + (u32)(BOFF + (wid*32+16)*AROW + ko)*4 + bofs);
        #pragma unroll
        for (int mt = 0; mt < 4; mt++)
            #pragma unroll
            for (int nt8 = 0; nt8 < 4; nt8++)
                mma16816(acc[mt][nt8], au[mt], bu[nt8]);
    }
}

__device__ __forceinline__ void stage_tile(int t, u32 sb, const __nv_bfloat16* Ag,
                                           const __nv_bfloat16* Bg, int kc, int stride){
    { int row = t>>2, seg = t&3;
      cp16(sb + (u32)(row*AROW + seg*4)*4, Ag + (size_t)row*stride + kc*32 + seg*8); }
    #pragma unroll
    for (int it = 0; it < 4; it++){
        int i = t + 256*it, row = i>>2, seg = i&3;
        cp16(sb + (u32)(BOFF + row*AROW + seg*4)*4, Bg + (size_t)row*stride + kc*32 + seg*8);
    }
    asm volatile("cp.async.commit_group;" ::: "memory");
}

// ===================== K2b: bf16 mma logits + softmax ======================
__global__ void __launch_bounds__(256, 2) k2b_logits(){
    extern __shared__ u32 smp[];
    float* red  = (float*)(smp + 3*BUFU);   // 512
    float* rmax = red + 512;
    float* rsum = rmax + 64;
    int t = threadIdx.x, wid = t>>5, lane = t&31;
    int g = lane>>2, t4 = lane&3;
    int qt = blockIdx.x, h = blockIdx.y, b = blockIdx.z;

    u32 aofs = (u32)((((lane&7) + ((lane>>3)&1)*8)*AROW + ((lane>>4)&1)*4)*4);
    u32 bofs = (u32)(((((lane>>4)&1)*8 + (lane&7))*AROW + ((lane>>3)&1)*4)*4);

    const __nv_bfloat16* Ag = g_xfeat + (size_t)(b*NQ + qt*64)*DX;
    const __nv_bfloat16* Bg = g_M     + (size_t)((b*HH+h)*NK)*DX;
    u32 sb = smem_u32(smp);

    float acc[4][4][4];
    #pragma unroll
    for (int mt = 0; mt < 4; mt++)
        #pragma unroll
        for (int nt8 = 0; nt8 < 4; nt8++)
            #pragma unroll
            for (int r = 0; r < 4; r++) acc[mt][nt8][r] = 0.f;

    stage_tile(t, sb, Ag, Bg, 0, DX);
    stage_tile(t, sb + BUFU*4, Ag, Bg, 1, DX);
    for (int kc = 0; kc < 17; kc++){
        asm volatile("cp.async.wait_group 1;" ::: "memory");
        __syncthreads();
        if (kc + 2 < 17)
            stage_tile(t, sb + (u32)(((kc+2)%3)*BUFU)*4, Ag, Bg, kc+2, DX);
        else
            asm volatile("cp.async.commit_group;" ::: "memory");
        gemm_chunk(sb + (u32)((kc%3)*BUFU)*4, acc, wid, aofs, bofs);
    }

    __syncthreads();
    #pragma unroll
    for (int mt = 0; mt < 4; mt++)
        #pragma unroll
        for (int i = 0; i < 2; i++){
            float m = -1e30f;
            #pragma unroll
            for (int nt8 = 0; nt8 < 4; nt8++)
                m = fmaxf(m, fmaxf(acc[mt][nt8][2*i], acc[mt][nt8][2*i+1]));
            m = fmaxf(m, __shfl_xor_sync(~0u, m, 1));
            m = fmaxf(m, __shfl_xor_sync(~0u, m, 2));
            if (t4 == 0) red[(mt*16 + g + i*8)*8 + wid] = m;
        }
    __syncthreads();
    if (t < 64){
        float m = red[t*8];
        #pragma unroll
        for (int j = 1; j < 8; j++) m = fmaxf(m, red[t*8+j]);
        rmax[t] = m;
    }
    __syncthreads();
    #pragma unroll
    for (int mt = 0; mt < 4; mt++)
        #pragma unroll
        for (int i = 0; i < 2; i++){
            float mm = rmax[mt*16 + g + i*8];
            float s = 0.f;
            #pragma unroll
            for (int nt8 = 0; nt8 < 4; nt8++){
                float e0 = __expf(acc[mt][nt8][2*i]   - mm);
                float e1 = __expf(acc[mt][nt8][2*i+1] - mm);
                acc[mt][nt8][2*i] = e0; acc[mt][nt8][2*i+1] = e1;
                s += e0 + e1;
            }
            s += __shfl_xor_sync(~0u, s, 1);
            s += __shfl_xor_sync(~0u, s, 2);
            if (t4 == 0) red[(mt*16 + g + i*8)*8 + wid] = s;
        }
    __syncthreads();
    if (t < 64){
        float s = red[t*8];
        #pragma unroll
        for (int j = 1; j < 8; j++) s += red[t*8+j];
        rsum[t] = 1.f/s;
    }
    __syncthreads();
    #pragma unroll
    for (int mt = 0; mt < 4; mt++)
        #pragma unroll
        for (int i = 0; i < 2; i++){
            int row = mt*16 + g + i*8;
            float inv = rsum[row];
            __nv_bfloat16* dst = g_attn + (size_t)(b*NQ + qt*64 + row)*2048 + h*NK + wid*32;
            #pragma unroll
            for (int nt8 = 0; nt8 < 4; nt8++)
                *(u32*)(dst + nt8*8 + t4*2) = bf2(acc[mt][nt8][2*i]*inv,
                                                  acc[mt][nt8][2*i+1]*inv);
        }
}

// ===================== K3: bf16 mma attn @ vprojT + residual ================
__global__ void __launch_bounds__(256, 2) k3_av(const float* __restrict__ hidden,
                                                const float* __restrict__ bo,
                                                float* __restrict__ out){
    extern __shared__ u32 smp[];
    int t = threadIdx.x, wid = t>>5, lane = t&31;
    int g = lane>>2, t4 = lane&3;
    int nt = blockIdx.x, qt = blockIdx.y, b = blockIdx.z;

    u32 aofs = (u32)((((lane&7) + ((lane>>3)&1)*8)*AROW + ((lane>>4)&1)*4)*4);
    u32 bofs = (u32)(((((lane>>4)&1)*8 + (lane&7))*AROW + ((lane>>3)&1)*4)*4);

    const __nv_bfloat16* Ag = g_attn   + (size_t)(b*NQ + qt*64)*2048;
    const __nv_bfloat16* Bg = g_vprojT + (size_t)(b*768 + nt*256)*2048;
    u32 sb = smem_u32(smp);

    float acc[4][4][4];
    #pragma unroll
    for (int mt = 0; mt < 4; mt++)
        #pragma unroll
        for (int nt8 = 0; nt8 < 4; nt8++)
            #pragma unroll
            for (int r = 0; r < 4; r++) acc[mt][nt8][r] = 0.f;

    stage_tile(t, sb, Ag, Bg, 0, 2048);
    stage_tile(t, sb + BUFU*4, Ag, Bg, 1, 2048);
    for (int kc = 0; kc < 64; kc++){
        asm volatile("cp.async.wait_group 1;" ::: "memory");
        __syncthreads();
        if (kc + 2 < 64)
            stage_tile(t, sb + (u32)(((kc+2)%3)*BUFU)*4, Ag, Bg, kc+2, 2048);
        else
            asm volatile("cp.async.commit_group;" ::: "memory");
        gemm_chunk(sb + (u32)((kc%3)*BUFU)*4, acc, wid, aofs, bofs);
    }

    #pragma unroll
    for (int mt = 0; mt < 4; mt++)
        #pragma unroll
        for (int i = 0; i < 2; i++){
            int row = qt*64 + mt*16 + g + i*8;
            const float* hb = hidden + (size_t)(b*NQ + row)*768;
            float*       ob = out    + (size_t)(b*NQ + row)*768;
            #pragma unroll
            for (int nt8 = 0; nt8 < 4; nt8++){
                int col = nt*256 + wid*32 + nt8*8 + t4*2;
                float2 hv = *(const float2*)(hb + col);
                float vx = acc[mt][nt8][2*i]   + hv.x;
                float vy = acc[mt][nt8][2*i+1] + hv.y;
                if ((col & 15) == 0) vx += bo[col >> 4];
                *(float2*)(ob + col) = make_float2(vx, vy);
            }
        }
}

// ===========================================================================
extern "C" void kernel_launch(void* const* d_in, const int* in_sizes, int n_in,
                              void* d_out, int out_size){
    const float* hidden = (const float*)d_in[0];
    const float* vision = (const float*)d_in[1];
    const float* lnw    = (const float*)d_in[2];
    const float* Wq     = (const float*)d_in[3];
    const float* bq     = (const float*)d_in[4];
    const float* Wkv    = (const float*)d_in[5];
    const float* bkv    = (const float*)d_in[6];
    const float* Wo     = (const float*)d_in[7];
    const float* bo     = (const float*)d_in[8];
    const float* daa    = (const float*)d_in[9];
    float* out = (float*)d_out;

    const int s2x = (16*768 + 16)*4;
    const int s1a = (768*20)*4;                       // 61440
    const int s1b = (11520 + 2*6144)*4;               // 95232
    const int s2b = (3*BUFU)*4 + (512 + 64 + 64)*4;   // 79360
    const int s3  = (3*BUFU)*4;                        // 76800
    cudaFuncSetAttribute(k2x_xfeat, cudaFuncAttributeMaxDynamicSharedMemorySize, s2x);
    cudaFuncSetAttribute(k1a_kv,    cudaFuncAttributeMaxDynamicSharedMemorySize, s1a);
    cudaFuncSetAttribute(k1b_vproj, cudaFuncAttributeMaxDynamicSharedMemorySize, s1b);
    cudaFuncSetAttribute(k2b_logits,cudaFuncAttributeMaxDynamicSharedMemorySize, s2b);
    cudaFuncSetAttribute(k3_av,     cudaFuncAttributeMaxDynamicSharedMemorySize, s3);

    k0a_prep  <<<64, 256>>>(Wq, Wo, daa);                      // 0
    k0b_prep  <<<64, 256>>>(Wkv);                              // 1
    k2x_xfeat <<<dim3(NQ/16, BB), 256, s2x>>>(hidden, lnw);    // 2
    k1a_kv    <<<dim3(NK/16, 3, BB), 256, s1a>>>(vision, bkv); // 3 (profiled)
    k1b_vproj <<<dim3(3, HH, BB), 256, s1b>>>();               // 4
    k2m_M     <<<dim3(NK/32, HH, BB), 256>>>(bq);              // 5
    k2b_logits<<<dim3(NQ/64, HH, BB), 256, s2b>>>();           // 6
    k3_av     <<<dim3(3, NQ/64, BB), 256, s3>>>(hidden, bo, out); // 7
}

// round 16
// speedup vs baseline: 2.0494x; 1.2115x over previous
#include <cuda_runtime.h>
#include <cuda_bf16.h>
#include <math.h>
#include <stdint.h>

#define BB 8
#define NQ 1024
#define NK 256
#define HH 8
#define DF 528
#define DFP 576
#define DX 544

typedef unsigned long long u64;
typedef unsigned int u32;

__constant__ int c_cg[11]    = {0,1,1,1,2,2,2,3,3,3,3};
__constant__ int c_comps[11] = {0,2,3,4,8,9,10,14,11,12,13};
__constant__ int c_grade[16] = {0,1,1,1,1,2,2,2,2,2,2,3,3,3,3,4};
__constant__ int c_jsmap[16] = {0,-1,1,2,3,-1,-1,-1,4,5,6,8,9,10,7,-1};

__device__ float g_WqT [5*48*384];
__device__ float g_WoT [5*384*48];
__device__ float g_sp  [8];
__device__ __nv_bfloat16 g_Wkvb  [5*768*48];
__device__ __nv_bfloat16 g_xv    [(size_t)BB*16*NK*48];
__device__ __nv_bfloat16 g_xfeat [(size_t)BB*NQ*DX];
__device__ __nv_bfloat16 g_M     [(size_t)BB*HH*NK*DX];
__device__ float         g_kfeatT[(size_t)BB*HH*NK*DFP];
__device__ float         g_vtmp  [(size_t)BB*HH*16*12288];
__device__ __nv_bfloat16 g_vprojT[(size_t)BB*768*2048];
__device__ __nv_bfloat16 g_attn  [(size_t)BB*NQ*2048];

__device__ __forceinline__ u64 pk2(float lo, float hi){
    u64 u; asm("mov.b64 %0,{%1,%2};" : "=l"(u) : "f"(lo), "f"(hi)); return u;
}
__device__ __forceinline__ void upk2(u64 u, float& lo, float& hi){
    asm("mov.b64 {%0,%1},%2;" : "=f"(lo), "=f"(hi) : "l"(u));
}
__device__ __forceinline__ u64 f2fma(u64 a, u64 b, u64 c){
    u64 d; asm("fma.rn.f32x2 %0,%1,%2,%3;" : "=l"(d) : "l"(a), "l"(b), "l"(c)); return d;
}
__device__ __forceinline__ u32 bf2(float lo, float hi){
    u32 r; asm("cvt.rn.bf16x2.f32 %0,%1,%2;" : "=r"(r) : "f"(hi), "f"(lo)); return r;
}
__device__ __forceinline__ u32 smem_u32(const void* p){
    u32 a; asm("{ .reg .u64 t; cvta.to.shared.u64 t, %1; cvt.u32.u64 %0, t; }" : "=r"(a) : "l"(p));
    return a;
}
__device__ __forceinline__ void mma16816(float* d, const u32* a, const u32* b){
    asm volatile("mma.sync.aligned.m16n8k16.row.col.f32.bf16.bf16.f32 "
        "{%0,%1,%2,%3},{%4,%5,%6,%7},{%8,%9},{%0,%1,%2,%3};"
        : "+f"(d[0]), "+f"(d[1]), "+f"(d[2]), "+f"(d[3])
        : "r"(a[0]), "r"(a[1]), "r"(a[2]), "r"(a[3]), "r"(b[0]), "r"(b[1]));
}
__device__ __forceinline__ void ldsm4(u32& r0, u32& r1, u32& r2, u32& r3, u32 addr){
    asm volatile("ldmatrix.sync.aligned.m8n8.x4.shared.b16 {%0,%1,%2,%3},[%4];"
        : "=r"(r0), "=r"(r1), "=r"(r2), "=r"(r3) : "r"(addr));
}
__device__ __forceinline__ void cp16(u32 sdst, const void* gsrc){
    asm volatile("cp.async.cg.shared.global [%0], [%1], 16;" :: "r"(sdst), "l"(gsrc));
}

// ============ K0a: WqT + WoT transposes + softplus ==========================
__global__ void k0a_prep(const float* __restrict__ Wq, const float* __restrict__ Wo,
                         const float* __restrict__ daa){
    int stride = gridDim.x * blockDim.x;
    int gid = blockIdx.x * blockDim.x + threadIdx.x;
    for (int idx = gid; idx < 5*384*48; idx += stride){
        int g = idx/(384*48), rem = idx%(384*48), o = rem/48, i = rem%48;
        g_WqT[(g*48+i)*384+o] = Wq[idx];
    }
    for (int idx = gid; idx < 5*48*384; idx += stride){
        int g = idx/(48*384), rem = idx%(48*384), o = rem/384, i = rem%384;
        g_WoT[(g*384+i)*48+o] = Wo[idx];
    }
    if (gid < 8){
        float x = daa[gid];
        g_sp[gid] = (x > 20.f) ? x : log1pf(expf(x));
    }
}

// ============ K0b: Wkv -> bf16 (original [g][o][in] layout) =================
__global__ void k0b_prep(const float* __restrict__ Wkv){
    int stride = gridDim.x * blockDim.x;
    int gid = blockIdx.x * blockDim.x + threadIdx.x;
    for (int idx = gid; idx < 5*768*48; idx += stride)
        g_Wkvb[idx] = __float2bfloat16(Wkv[idx]);
}

// ============ K1x: vision -> xv[b][c][k][48] bf16 ===========================
__global__ void __launch_bounds__(256) k1x_xv(const float* __restrict__ vision){
    extern __shared__ float sv[];    // 16*768
    int b = blockIdx.y, k0 = blockIdx.x*16, t = threadIdx.x;
    const float* src = vision + (size_t)(b*NK+k0)*768;
    for (int idx = t; idx < 16*768; idx += 256) sv[idx] = src[idx];
    __syncthreads();
    for (int idx = t; idx < 16*768; idx += 256){
        int r = idx/768, rem = idx - r*768, c = rem/48, in = rem - c*48;
        g_xv[((size_t)(b*16+c)*NK + k0 + r)*48 + in] =
            __float2bfloat16(sv[r*768 + in*16 + c]);
    }
}

// ============ K1m: bf16 HMMA kv projection -> kfeatT / vtmp =================
#define KROW 28

__global__ void __launch_bounds__(256) k1m_kv(const float* __restrict__ bkv){
    extern __shared__ u32 smk[];     // A 64*28 + B 256*28 u32
    int t = threadIdx.x, wid = t>>5, lane = t&31;
    int g = lane>>2, t4 = lane&3;
    int bx = blockIdx.x, c = blockIdx.y, b = blockIdx.z;
    int k0 = (bx & 3)*64, o0 = (bx >> 2)*256;
    u32 sb = smem_u32(smk);

    const __nv_bfloat16* Ag = g_xv + ((size_t)(b*16+c)*NK + k0)*48;
    #pragma unroll
    for (int it = 0; it < 2; it++){
        int idx = t + 256*it;
        if (idx < 384){
            int row = idx/6, seg = idx - row*6;
            cp16(sb + (u32)(row*KROW + seg*4)*4, Ag + (size_t)row*48 + seg*8);
        }
    }
    const __nv_bfloat16* Bg = g_Wkvb + (size_t)(c_grade[c]*768 + o0)*48;
    #pragma unroll
    for (int it = 0; it < 6; it++){
        int idx = t + 256*it;
        int row = idx/6, seg = idx - row*6;
        cp16(sb + (u32)(64*KROW + row*KROW + seg*4)*4, Bg + (size_t)row*48 + seg*8);
    }
    asm volatile("cp.async.commit_group;" ::: "memory");
    asm volatile("cp.async.wait_group 0;" ::: "memory");
    __syncthreads();

    u32 aofs = (u32)((((lane&7) + ((lane>>3)&1)*8)*KROW + ((lane>>4)&1)*4)*4);
    u32 bofs = (u32)(((((lane>>4)&1)*8 + (lane&7))*KROW + ((lane>>3)&1)*4)*4);

    float acc[4][4][4];
    #pragma unroll
    for (int mt = 0; mt < 4; mt++)
        #pragma unroll
        for (int nt8 = 0; nt8 < 4; nt8++)
            #pragma unroll
            for (int r = 0; r < 4; r++) acc[mt][nt8][r] = 0.f;

    #pragma unroll
    for (int kk = 0; kk < 3; kk++){
        u32 au[4][4];
        #pragma unroll
        for (int mt = 0; mt < 4; mt++)
            ldsm4(au[mt][0], au[mt][1], au[mt][2], au[mt][3],
                  sb + (u32)(mt*16*KROW + kk*8)*4 + aofs);
        u32 bu[4][2];
        ldsm4(bu[0][0], bu[0][1], bu[1][0], bu[1][1],
              sb + (u32)(64*KROW + wid*32*KROW + kk*8)*4 + bofs);
        ldsm4(bu[2][0], bu[2][1], bu[3][0], bu[3][1],
              sb + (u32)(64*KROW + (wid*32+16)*KROW + kk*8)*4 + bofs);
        #pragma unroll
        for (int mt = 0; mt < 4; mt++)
            #pragma unroll
            for (int nt8 = 0; nt8 < 4; nt8++)
                mma16816(acc[mt][nt8], au[mt], bu[nt8]);
    }

    // ---- epilogue: scatter to kfeatT / vtmp ----
    const float INVS = 0.051031036307982884f;   // 1/sqrt(384)
    int js = c_jsmap[c];
    #pragma unroll
    for (int mt = 0; mt < 4; mt++)
        #pragma unroll
        for (int i = 0; i < 2; i++){
            int key = k0 + mt*16 + g + i*8;
            #pragma unroll
            for (int nt8 = 0; nt8 < 4; nt8++){
                int col = o0 + wid*32 + nt8*8 + t4*2;
                float v0 = acc[mt][nt8][2*i], v1 = acc[mt][nt8][2*i+1];
                if (c == 0){ v0 += bkv[col]; v1 += bkv[col+1]; }
                if (col < 384){
                    if (js >= 0){
                        int h = col/48, i48 = col - h*48;
                        float sc = (js < 8) ? INVS : g_sp[h]*(2.f/48.f);
                        int f = (js < 8) ? js*48 : 384 + (js-8)*48;
                        size_t rb = (size_t)((b*HH+h)*NK + key)*DFP + f + i48;
                        g_kfeatT[rb]     = v0*sc;
                        g_kfeatT[rb + 1] = v1*sc;
                    }
                } else {
                    int vc = col - 384, h = vc/48, i48 = vc - h*48;
                    float* vb = g_vtmp + ((size_t)((b*HH+h)*16 + (key>>4)))*12288;
                    vb[(i48*16 + c)*16 + (key&15)]     = v0;
                    vb[((i48+1)*16 + c)*16 + (key&15)] = v1;
                }
            }
        }
}

// ============ K2x: rmsnorm + reorder -> xfeat [row][544] (bf16) =============
__global__ void __launch_bounds__(256) k2x_xfeat(const float* __restrict__ hidden,
                                                 const float* __restrict__ lnw){
    extern __shared__ float sx[];
    float* rows = sx;               // 16*768
    float* rsq  = sx + 16*768;      // 16
    int b = blockIdx.y, q0 = blockIdx.x*16, t = threadIdx.x;
    const float* hrow = hidden + (size_t)(b*NQ+q0)*768;
    for (int idx = t; idx < 16*768; idx += 256) rows[idx] = hrow[idx];
    __syncthreads();
    { int r = t>>4, sub = t&15; float s = 0.f;
      for (int e = sub; e < 768; e += 16){ float v = rows[r*768+e]; s += v*v; }
      s += __shfl_xor_sync(~0u, s, 1);
      s += __shfl_xor_sync(~0u, s, 2);
      s += __shfl_xor_sync(~0u, s, 4);
      s += __shfl_xor_sync(~0u, s, 8);
      if (sub == 0) rsq[r] = rsqrtf(s*(1.f/48.f) + 1e-6f);
    }
    __syncthreads();
    __nv_bfloat16* dst = g_xfeat + (size_t)(b*NQ+q0)*DX;
    for (int idx = t; idx < 16*DX; idx += 256){
        int r = idx/DX, d = idx - r*DX;
        float val;
        if (d < DF){
            int js = d/48, in = d - js*48;
            val = rows[r*768 + in*16 + c_comps[js]] * rsq[r] * lnw[in];
        } else val = (d == DF) ? 1.f : 0.f;
        dst[idx] = __float2bfloat16(val);
    }
}

// ========== K1b: vprojT via cp.async pipelined subtiles =====================
__global__ void __launch_bounds__(256) k1b_vproj(){
    extern __shared__ float sm2[];
    float* w_s = sm2;             // 11520
    float* v_s = sm2 + 11520;     // 2 * 6144
    int sl = blockIdx.x, h = blockIdx.y, b = blockIdx.z, t = threadIdx.x;

    for (int idx = t; idx < 11520; idx += 256){
        int g = idx/2304, r = idx - g*2304;
        w_s[idx] = g_WoT[(g*384 + h*48)*48 + r];
    }
    int j = sl*256 + t;
    int o48 = j % 48, c = j / 48;
    int g = c_grade[c];
    const float* Vg = g_vtmp + (size_t)((b*HH+h)*16)*12288;
    u32 sb = smem_u32(v_s);
    const float* wp = w_s + g*2304 + o48;

    {   // stage s = 0
        const float* src = Vg;
        #pragma unroll
        for (int it = 0; it < 6; it++){
            int idx = t + 256*it;
            int row = idx>>1, part = idx&1;
            cp16(sb + (u32)(row*8 + part*4)*4, src + row*16 + part*4);
        }
        asm volatile("cp.async.commit_group;" ::: "memory");
    }

    for (int s = 0; s < 32; s++){
        asm volatile("cp.async.wait_group 0;" ::: "memory");
        __syncthreads();
        if (s + 1 < 32){
            const float* src = Vg + (size_t)((s+1)>>1)*12288 + ((s+1)&1)*8;
            int buf = (s+1)&1;
            #pragma unroll
            for (int it = 0; it < 6; it++){
                int idx = t + 256*it;
                int row = idx>>1, part = idx&1;
                cp16(sb + (u32)(buf*6144 + row*8 + part*4)*4, src + row*16 + part*4);
            }
            asm volatile("cp.async.commit_group;" ::: "memory");
        } else {
            asm volatile("cp.async.commit_group;" ::: "memory");
        }
        const float* vp0 = v_s + (s&1)*6144 + c*8;
        u64 acc[4] = {0ull, 0ull, 0ull, 0ull};
        #pragma unroll 8
        for (int i = 0; i < 48; i++){
            float w = wp[i*48];
            u64 w2 = pk2(w, w);
            const float* vp = vp0 + i*128;
            acc[0] = f2fma(*(const u64*)(vp    ), w2, acc[0]);
            acc[1] = f2fma(*(const u64*)(vp + 2), w2, acc[1]);
            acc[2] = f2fma(*(const u64*)(vp + 4), w2, acc[2]);
            acc[3] = f2fma(*(const u64*)(vp + 6), w2, acc[3]);
        }
        u32 r4[4];
        #pragma unroll
        for (int kp = 0; kp < 4; kp++){
            float lo, hi; upk2(acc[kp], lo, hi);
            r4[kp] = bf2(lo, hi);
        }
        __nv_bfloat16* dst = g_vprojT + (size_t)(b*768 + o48*16 + c)*2048
                           + h*256 + (s>>1)*16 + (s&1)*8;
        *(uint4*)dst = *(const uint4*)r4;
        __syncthreads();
    }
}

// ======= K2m: M[b,h][k][544] (bf16) — 512 CTAs, 32 keys each ================
__global__ void __launch_bounds__(256) k2m_M(const float* __restrict__ bq){
    __shared__ float kfT[48*34];
    __shared__ float ws [48*49];
    __shared__ float mT [48*34];
    __shared__ float kb32[32];
    __shared__ float ss32[32];
    int kt0 = blockIdx.x*32, h = blockIdx.y, b = blockIdx.z, t = threadIdx.x;
    size_t kbase = (size_t)((b*HH+h)*NK) + kt0;
    if (t < 32) ss32[t] = 0.f;

    for (int js = 0; js < 11; js++){
        int g = c_cg[js];
        __syncthreads();
        #pragma unroll
        for (int r = 0; r < 6; r++){
            int idx = t + 256*r;
            if (idx < 1536){
                int k = idx/48, j = idx - k*48;
                kfT[j*34 + k] = g_kfeatT[(kbase + k)*DFP + js*48 + j];
            }
        }
        #pragma unroll
        for (int r = 0; r < 9; r++){
            int idx = t + 256*r;
            if (idx < 2304){
                int c = idx/48, j = idx - c*48;
                ws[j*49 + c] = g_WqT[(g*48+c)*384 + h*48 + j];
            }
        }
        __syncthreads();
        if (js == 0 && t < 32){
            float s = 0.f;
            #pragma unroll 8
            for (int j = 0; j < 48; j++) s += bq[h*48+j]*kfT[j*34 + t];
            kb32[t] = s;
        }
        if (js >= 8 && t < 32){
            float s = 0.f;
            #pragma unroll 8
            for (int j = 0; j < 48; j++){ float v = kfT[j*34 + t]; s += v*v; }
            ss32[t] += s;
        }
        #pragma unroll
        for (int r = 0; r < 3; r++){
            int o = t + 256*r;
            int c = o >> 4, kp = o & 15;
            u64 acc = 0ull;
            #pragma unroll 8
            for (int j = 0; j < 48; j++){
                float w = ws[j*49 + c];
                acc = f2fma(*(const u64*)&kfT[j*34 + 2*kp], pk2(w, w), acc);
            }
            *(u64*)&mT[c*34 + 2*kp] = acc;
        }
        __syncthreads();
        #pragma unroll
        for (int r = 0; r < 6; r++){
            int idx = t + 256*r;
            if (idx < 1536){
                int k = idx/48, c = idx - k*48;
                g_M[(kbase + k)*DX + js*48 + c] = __float2bfloat16(mT[c*34 + k]);
            }
        }
    }
    __syncthreads();
    float sp = g_sp[h];
    #pragma unroll
    for (int r = 0; r < 2; r++){
        int idx = t + 256*r;
        int k = idx >> 4, cc = idx & 15;
        float v = (cc == 0) ? (kb32[k] - (12.f/sp)*ss32[k]) : 0.f;
        g_M[(kbase + k)*DX + DF + cc] = __float2bfloat16(v);
    }
}

// ============ bf16 GEMM core: 64 rows x 256 cols, ldmatrix + mma16816 =======
#define AROW 20
#define BOFF 1280
#define BUFU 6400

__device__ __forceinline__ void gemm_chunk(u32 base, float acc[4][4][4],
                                           int wid, u32 aofs, u32 bofs){
    #pragma unroll
    for (int k16 = 0; k16 < 2; k16++){
        int ko = k16*8;
        u32 au[4][4];
        #pragma unroll
        for (int mt = 0; mt < 4; mt++)
            ldsm4(au[mt][0], au[mt][1], au[mt][2], au[mt][3],
                  base + (u32)(mt*16*AROW + ko)*4 + aofs);
        u32 bu[4][2];
        ldsm4(bu[0][0], bu[0][1], bu[1][0], bu[1][1],
              base + (u32)(BOFF + wid*32*AROW + ko)*4 + bofs);
        ldsm4(bu[2][0], bu[2][1], bu[3][0], bu[3][1],
              base + (u32)(BOFF + (wid*32+16)*AROW + ko)*4 + bofs);
        #pragma unroll
        for (int mt = 0; mt < 4; mt++)
            #pragma unroll
            for (int nt8 = 0; nt8 < 4; nt8++)
                mma16816(acc[mt][nt8], au[mt], bu[nt8]);
    }
}

__device__ __forceinline__ void stage_tile(int t, u32 sb, const __nv_bfloat16* Ag,
                                           const __nv_bfloat16* Bg, int kc, int stride){
    { int row = t>>2, seg = t&3;
      cp16(sb + (u32)(row*AROW + seg*4)*4, Ag + (size_t)row*stride + kc*32 + seg*8); }
    #pragma unroll
    for (int it = 0; it < 4; it++){
        int i = t + 256*it, row = i>>2, seg = i&3;
        cp16(sb + (u32)(BOFF + row*AROW + seg*4)*4, Bg + (size_t)row*stride + kc*32 + seg*8);
    }
    asm volatile("cp.async.commit_group;" ::: "memory");
}

// ===================== K2b: bf16 mma logits + softmax ======================
__global__ void __launch_bounds__(256, 2) k2b_logits(){
    extern __shared__ u32 smp[];
    float* red  = (float*)(smp + 3*BUFU);
    float* rmax = red + 512;
    float* rsum = rmax + 64;
    int t = threadIdx.x, wid = t>>5, lane = t&31;
    int g = lane>>2, t4 = lane&3;
    int qt = blockIdx.x, h = blockIdx.y, b = blockIdx.z;

    u32 aofs = (u32)((((lane&7) + ((lane>>3)&1)*8)*AROW + ((lane>>4)&1)*4)*4);
    u32 bofs = (u32)(((((lane>>4)&1)*8 + (lane&7))*AROW + ((lane>>3)&1)*4)*4);

    const __nv_bfloat16* Ag = g_xfeat + (size_t)(b*NQ + qt*64)*DX;
    const __nv_bfloat16* Bg = g_M     + (size_t)((b*HH+h)*NK)*DX;
    u32 sb = smem_u32(smp);

    float acc[4][4][4];
    #pragma unroll
    for (int mt = 0; mt < 4; mt++)
        #pragma unroll
        for (int nt8 = 0; nt8 < 4; nt8++)
            #pragma unroll
            for (int r = 0; r < 4; r++) acc[mt][nt8][r] = 0.f;

    stage_tile(t, sb, Ag, Bg, 0, DX);
    stage_tile(t, sb + BUFU*4, Ag, Bg, 1, DX);
    for (int kc = 0; kc < 17; kc++){
        asm volatile("cp.async.wait_group 1;" ::: "memory");
        __syncthreads();
        if (kc + 2 < 17)
            stage_tile(t, sb + (u32)(((kc+2)%3)*BUFU)*4, Ag, Bg, kc+2, DX);
        else
            asm volatile("cp.async.commit_group;" ::: "memory");
        gemm_chunk(sb + (u32)((kc%3)*BUFU)*4, acc, wid, aofs, bofs);
    }

    __syncthreads();
    #pragma unroll
    for (int mt = 0; mt < 4; mt++)
        #pragma unroll
        for (int i = 0; i < 2; i++){
            float m = -1e30f;
            #pragma unroll
            for (int nt8 = 0; nt8 < 4; nt8++)
                m = fmaxf(m, fmaxf(acc[mt][nt8][2*i], acc[mt][nt8][2*i+1]));
            m = fmaxf(m, __shfl_xor_sync(~0u, m, 1));
            m = fmaxf(m, __shfl_xor_sync(~0u, m, 2));
            if (t4 == 0) red[(mt*16 + g + i*8)*8 + wid] = m;
        }
    __syncthreads();
    if (t < 64){
        float m = red[t*8];
        #pragma unroll
        for (int j = 1; j < 8; j++) m = fmaxf(m, red[t*8+j]);
        rmax[t] = m;
    }
    __syncthreads();
    #pragma unroll
    for (int mt = 0; mt < 4; mt++)
        #pragma unroll
        for (int i = 0; i < 2; i++){
            float mm = rmax[mt*16 + g + i*8];
            float s = 0.f;
            #pragma unroll
            for (int nt8 = 0; nt8 < 4; nt8++){
                float e0 = __expf(acc[mt][nt8][2*i]   - mm);
                float e1 = __expf(acc[mt][nt8][2*i+1] - mm);
                acc[mt][nt8][2*i] = e0; acc[mt][nt8][2*i+1] = e1;
                s += e0 + e1;
            }
            s += __shfl_xor_sync(~0u, s, 1);
            s += __shfl_xor_sync(~0u, s, 2);
            if (t4 == 0) red[(mt*16 + g + i*8)*8 + wid] = s;
        }
    __syncthreads();
    if (t < 64){
        float s = red[t*8];
        #pragma unroll
        for (int j = 1; j < 8; j++) s += red[t*8+j];
        rsum[t] = 1.f/s;
    }
    __syncthreads();
    #pragma unroll
    for (int mt = 0; mt < 4; mt++)
        #pragma unroll
        for (int i = 0; i < 2; i++){
            int row = mt*16 + g + i*8;
            float inv = rsum[row];
            __nv_bfloat16* dst = g_attn + (size_t)(b*NQ + qt*64 + row)*2048 + h*NK + wid*32;
            #pragma unroll
            for (int nt8 = 0; nt8 < 4; nt8++)
                *(u32*)(dst + nt8*8 + t4*2) = bf2(acc[mt][nt8][2*i]*inv,
                                                  acc[mt][nt8][2*i+1]*inv);
        }
}

// ===================== K3: bf16 mma attn @ vprojT + residual ================
__global__ void __launch_bounds__(256, 2) k3_av(const float* __restrict__ hidden,
                                                const float* __restrict__ bo,
                                                float* __restrict__ out){
    extern __shared__ u32 smp[];
    int t = threadIdx.x, wid = t>>5, lane = t&31;
    int g = lane>>2, t4 = lane&3;
    int nt = blockIdx.x, qt = blockIdx.y, b = blockIdx.z;

    u32 aofs = (u32)((((lane&7) + ((lane>>3)&1)*8)*AROW + ((lane>>4)&1)*4)*4);
    u32 bofs = (u32)(((((lane>>4)&1)*8 + (lane&7))*AROW + ((lane>>3)&1)*4)*4);

    const __nv_bfloat16* Ag = g_attn   + (size_t)(b*NQ + qt*64)*2048;
    const __nv_bfloat16* Bg = g_vprojT + (size_t)(b*768 + nt*256)*2048;
    u32 sb = smem_u32(smp);

    float acc[4][4][4];
    #pragma unroll
    for (int mt = 0; mt < 4; mt++)
        #pragma unroll
        for (int nt8 = 0; nt8 < 4; nt8++)
            #pragma unroll
            for (int r = 0; r < 4; r++) acc[mt][nt8][r] = 0.f;

    stage_tile(t, sb, Ag, Bg, 0, 2048);
    stage_tile(t, sb + BUFU*4, Ag, Bg, 1, 2048);
    for (int kc = 0; kc < 64; kc++){
        asm volatile("cp.async.wait_group 1;" ::: "memory");
        __syncthreads();
        if (kc + 2 < 64)
            stage_tile(t, sb + (u32)(((kc+2)%3)*BUFU)*4, Ag, Bg, kc+2, 2048);
        else
            asm volatile("cp.async.commit_group;" ::: "memory");
        gemm_chunk(sb + (u32)((kc%3)*BUFU)*4, acc, wid, aofs, bofs);
    }

    #pragma unroll
    for (int mt = 0; mt < 4; mt++)
        #pragma unroll
        for (int i = 0; i < 2; i++){
            int row = qt*64 + mt*16 + g + i*8;
            const float* hb = hidden + (size_t)(b*NQ + row)*768;
            float*       ob = out    + (size_t)(b*NQ + row)*768;
            #pragma unroll
            for (int nt8 = 0; nt8 < 4; nt8++){
                int col = nt*256 + wid*32 + nt8*8 + t4*2;
                float2 hv = *(const float2*)(hb + col);
                float vx = acc[mt][nt8][2*i]   + hv.x;
                float vy = acc[mt][nt8][2*i+1] + hv.y;
                if ((col & 15) == 0) vx += bo[col >> 4];
                *(float2*)(ob + col) = make_float2(vx, vy);
            }
        }
}

// ===========================================================================
extern "C" void kernel_launch(void* const* d_in, const int* in_sizes, int n_in,
                              void* d_out, int out_size){
    const float* hidden = (const float*)d_in[0];
    const float* vision = (const float*)d_in[1];
    const float* lnw    = (const float*)d_in[2];
    const float* Wq     = (const float*)d_in[3];
    const float* bq     = (const float*)d_in[4];
    const float* Wkv    = (const float*)d_in[5];
    const float* bkv    = (const float*)d_in[6];
    const float* Wo     = (const float*)d_in[7];
    const float* bo     = (const float*)d_in[8];
    const float* daa    = (const float*)d_in[9];
    float* out = (float*)d_out;

    const int s1x = (16*768)*4;                       // 49152
    const int s1m = (320*KROW)*4;                     // 35840
    const int s2x = (16*768 + 16)*4;
    const int s1b = (11520 + 2*6144)*4;               // 95232
    const int s2b = (3*BUFU)*4 + (512 + 64 + 64)*4;   // 79360
    const int s3  = (3*BUFU)*4;                        // 76800
    cudaFuncSetAttribute(k1x_xv,    cudaFuncAttributeMaxDynamicSharedMemorySize, s1x);
    cudaFuncSetAttribute(k1m_kv,    cudaFuncAttributeMaxDynamicSharedMemorySize, s1m);
    cudaFuncSetAttribute(k2x_xfeat, cudaFuncAttributeMaxDynamicSharedMemorySize, s2x);
    cudaFuncSetAttribute(k1b_vproj, cudaFuncAttributeMaxDynamicSharedMemorySize, s1b);
    cudaFuncSetAttribute(k2b_logits,cudaFuncAttributeMaxDynamicSharedMemorySize, s2b);
    cudaFuncSetAttribute(k3_av,     cudaFuncAttributeMaxDynamicSharedMemorySize, s3);

    k0a_prep  <<<64, 256>>>(Wq, Wo, daa);                       // 0
    k1x_xv    <<<dim3(NK/16, BB), 256, s1x>>>(vision);          // 1
    k0b_prep  <<<64, 256>>>(Wkv);                               // 2
    k1m_kv    <<<dim3(12, 16, BB), 256, s1m>>>(bkv);            // 3 (profiled)
    k2x_xfeat <<<dim3(NQ/16, BB), 256, s2x>>>(hidden, lnw);     // 4
    k1b_vproj <<<dim3(3, HH, BB), 256, s1b>>>();                // 5
    k2m_M     <<<dim3(NK/32, HH, BB), 256>>>(bq);               // 6
    k2b_logits<<<dim3(NQ/64, HH, BB), 256, s2b>>>();            // 7
    k3_av     <<<dim3(3, NQ/64, BB), 256, s3>>>(hidden, bo, out); // 8
}

// round 17
// speedup vs baseline: 2.0531x; 1.0018x over previous
#include <cuda_runtime.h>
#include <cuda_bf16.h>
#include <math.h>
#include <stdint.h>

#define BB 8
#define NQ 1024
#define NK 256
#define HH 8
#define DF 528
#define DFP 576
#define DX 544

typedef unsigned long long u64;
typedef unsigned int u32;

__constant__ int c_cg[11]    = {0,1,1,1,2,2,2,3,3,3,3};
__constant__ int c_comps[11] = {0,2,3,4,8,9,10,14,11,12,13};
__constant__ int c_grade[16] = {0,1,1,1,1,2,2,2,2,2,2,3,3,3,3,4};
__constant__ int c_jsmap[16] = {0,-1,1,2,3,-1,-1,-1,4,5,6,8,9,10,7,-1};

__device__ float g_WqT [5*48*384];
__device__ float g_WoT [5*384*48];
__device__ float g_sp  [8];
__device__ __nv_bfloat16 g_Wkvb  [5*768*48];
__device__ __nv_bfloat16 g_xv    [(size_t)BB*16*NK*48];
__device__ __nv_bfloat16 g_xfeat [(size_t)BB*NQ*DX];
__device__ __nv_bfloat16 g_M     [(size_t)BB*HH*NK*DX];
__device__ float         g_kfeatT[(size_t)BB*HH*NK*DFP];
__device__ float         g_vtmp  [(size_t)BB*HH*16*12288];
__device__ __nv_bfloat16 g_vprojT[(size_t)BB*768*2048];
__device__ __nv_bfloat16 g_attn  [(size_t)BB*NQ*2048];

__device__ __forceinline__ u64 pk2(float lo, float hi){
    u64 u; asm("mov.b64 %0,{%1,%2};" : "=l"(u) : "f"(lo), "f"(hi)); return u;
}
__device__ __forceinline__ void upk2(u64 u, float& lo, float& hi){
    asm("mov.b64 {%0,%1},%2;" : "=f"(lo), "=f"(hi) : "l"(u));
}
__device__ __forceinline__ u64 f2fma(u64 a, u64 b, u64 c){
    u64 d; asm("fma.rn.f32x2 %0,%1,%2,%3;" : "=l"(d) : "l"(a), "l"(b), "l"(c)); return d;
}
__device__ __forceinline__ u32 bf2(float lo, float hi){
    u32 r; asm("cvt.rn.bf16x2.f32 %0,%1,%2;" : "=r"(r) : "f"(hi), "f"(lo)); return r;
}
__device__ __forceinline__ u32 smem_u32(const void* p){
    u32 a; asm("{ .reg .u64 t; cvta.to.shared.u64 t, %1; cvt.u32.u64 %0, t; }" : "=r"(a) : "l"(p));
    return a;
}
__device__ __forceinline__ void mma16816(float* d, const u32* a, const u32* b){
    asm volatile("mma.sync.aligned.m16n8k16.row.col.f32.bf16.bf16.f32 "
        "{%0,%1,%2,%3},{%4,%5,%6,%7},{%8,%9},{%0,%1,%2,%3};"
        : "+f"(d[0]), "+f"(d[1]), "+f"(d[2]), "+f"(d[3])
        : "r"(a[0]), "r"(a[1]), "r"(a[2]), "r"(a[3]), "r"(b[0]), "r"(b[1]));
}
__device__ __forceinline__ void ldsm4(u32& r0, u32& r1, u32& r2, u32& r3, u32 addr){
    asm volatile("ldmatrix.sync.aligned.m8n8.x4.shared.b16 {%0,%1,%2,%3},[%4];"
        : "=r"(r0), "=r"(r1), "=r"(r2), "=r"(r3) : "r"(addr));
}
__device__ __forceinline__ void cp16(u32 sdst, const void* gsrc){
    asm volatile("cp.async.cg.shared.global [%0], [%1], 16;" :: "r"(sdst), "l"(gsrc));
}

// ============ K0a: WqT + WoT transposes + softplus ==========================
__global__ void k0a_prep(const float* __restrict__ Wq, const float* __restrict__ Wo,
                         const float* __restrict__ daa){
    int stride = gridDim.x * blockDim.x;
    int gid = blockIdx.x * blockDim.x + threadIdx.x;
    for (int idx = gid; idx < 5*384*48; idx += stride){
        int g = idx/(384*48), rem = idx%(384*48), o = rem/48, i = rem%48;
        g_WqT[(g*48+i)*384+o] = Wq[idx];
    }
    for (int idx = gid; idx < 5*48*384; idx += stride){
        int g = idx/(48*384), rem = idx%(48*384), o = rem/384, i = rem%384;
        g_WoT[(g*384+i)*48+o] = Wo[idx];
    }
    if (gid < 8){
        float x = daa[gid];
        g_sp[gid] = (x > 20.f) ? x : log1pf(expf(x));
    }
}

// ============ K0b: Wkv -> bf16 (original [g][o][in] layout) =================
__global__ void k0b_prep(const float* __restrict__ Wkv){
    int stride = gridDim.x * blockDim.x;
    int gid = blockIdx.x * blockDim.x + threadIdx.x;
    for (int idx = gid; idx < 5*768*48; idx += stride)
        g_Wkvb[idx] = __float2bfloat16(Wkv[idx]);
}

// ============ K1x: vision -> xv[b][c][k][48] bf16 ===========================
__global__ void __launch_bounds__(256) k1x_xv(const float* __restrict__ vision){
    extern __shared__ float sv[];    // 16*768
    int b = blockIdx.y, k0 = blockIdx.x*16, t = threadIdx.x;
    const float* src = vision + (size_t)(b*NK+k0)*768;
    for (int idx = t; idx < 16*768; idx += 256) sv[idx] = src[idx];
    __syncthreads();
    for (int idx = t; idx < 16*768; idx += 256){
        int r = idx/768, rem = idx - r*768, c = rem/48, in = rem - c*48;
        g_xv[((size_t)(b*16+c)*NK + k0 + r)*48 + in] =
            __float2bfloat16(sv[r*768 + in*16 + c]);
    }
}

// ============ K1m: bf16 HMMA kv projection -> kfeatT / vtmp =================
#define KROW 28

__global__ void __launch_bounds__(256) k1m_kv(const float* __restrict__ bkv){
    extern __shared__ u32 smk[];     // A 64*28 + B 256*28 u32
    int t = threadIdx.x, wid = t>>5, lane = t&31;
    int g = lane>>2, t4 = lane&3;
    int bx = blockIdx.x, c = blockIdx.y, b = blockIdx.z;
    int k0 = (bx & 3)*64, o0 = (bx >> 2)*256;
    u32 sb = smem_u32(smk);

    const __nv_bfloat16* Ag = g_xv + ((size_t)(b*16+c)*NK + k0)*48;
    #pragma unroll
    for (int it = 0; it < 2; it++){
        int idx = t + 256*it;
        if (idx < 384){
            int row = idx/6, seg = idx - row*6;
            cp16(sb + (u32)(row*KROW + seg*4)*4, Ag + (size_t)row*48 + seg*8);
        }
    }
    const __nv_bfloat16* Bg = g_Wkvb + (size_t)(c_grade[c]*768 + o0)*48;
    #pragma unroll
    for (int it = 0; it < 6; it++){
        int idx = t + 256*it;
        int row = idx/6, seg = idx - row*6;
        cp16(sb + (u32)(64*KROW + row*KROW + seg*4)*4, Bg + (size_t)row*48 + seg*8);
    }
    asm volatile("cp.async.commit_group;" ::: "memory");
    asm volatile("cp.async.wait_group 0;" ::: "memory");
    __syncthreads();

    u32 aofs = (u32)((((lane&7) + ((lane>>3)&1)*8)*KROW + ((lane>>4)&1)*4)*4);
    u32 bofs = (u32)(((((lane>>4)&1)*8 + (lane&7))*KROW + ((lane>>3)&1)*4)*4);

    float acc[4][4][4];
    #pragma unroll
    for (int mt = 0; mt < 4; mt++)
        #pragma unroll
        for (int nt8 = 0; nt8 < 4; nt8++)
            #pragma unroll
            for (int r = 0; r < 4; r++) acc[mt][nt8][r] = 0.f;

    #pragma unroll
    for (int kk = 0; kk < 3; kk++){
        u32 au[4][4];
        #pragma unroll
        for (int mt = 0; mt < 4; mt++)
            ldsm4(au[mt][0], au[mt][1], au[mt][2], au[mt][3],
                  sb + (u32)(mt*16*KROW + kk*8)*4 + aofs);
        u32 bu[4][2];
        ldsm4(bu[0][0], bu[0][1], bu[1][0], bu[1][1],
              sb + (u32)(64*KROW + wid*32*KROW + kk*8)*4 + bofs);
        ldsm4(bu[2][0], bu[2][1], bu[3][0], bu[3][1],
              sb + (u32)(64*KROW + (wid*32+16)*KROW + kk*8)*4 + bofs);
        #pragma unroll
        for (int mt = 0; mt < 4; mt++)
            #pragma unroll
            for (int nt8 = 0; nt8 < 4; nt8++)
                mma16816(acc[mt][nt8], au[mt], bu[nt8]);
    }

    // ---- epilogue: scatter to kfeatT / vtmp ----
    const float INVS = 0.051031036307982884f;   // 1/sqrt(384)
    int js = c_jsmap[c];
    #pragma unroll
    for (int mt = 0; mt < 4; mt++)
        #pragma unroll
        for (int i = 0; i < 2; i++){
            int key = k0 + mt*16 + g + i*8;
            #pragma unroll
            for (int nt8 = 0; nt8 < 4; nt8++){
                int col = o0 + wid*32 + nt8*8 + t4*2;
                float v0 = acc[mt][nt8][2*i], v1 = acc[mt][nt8][2*i+1];
                if (c == 0){ v0 += bkv[col]; v1 += bkv[col+1]; }
                if (col < 384){
                    if (js >= 0){
                        int h = col/48, i48 = col - h*48;
                        float sc = (js < 8) ? INVS : g_sp[h]*(2.f/48.f);
                        int f = (js < 8) ? js*48 : 384 + (js-8)*48;
                        size_t rb = (size_t)((b*HH+h)*NK + key)*DFP + f + i48;
                        g_kfeatT[rb]     = v0*sc;
                        g_kfeatT[rb + 1] = v1*sc;
                    }
                } else {
                    int vc = col - 384, h = vc/48, i48 = vc - h*48;
                    float* vb = g_vtmp + ((size_t)((b*HH+h)*16 + (key>>4)))*12288;
                    vb[(i48*16 + c)*16 + (key&15)]     = v0;
                    vb[((i48+1)*16 + c)*16 + (key&15)] = v1;
                }
            }
        }
}

// ============ K2x: rmsnorm + reorder -> xfeat [row][544] (bf16) =============
__global__ void __launch_bounds__(256) k2x_xfeat(const float* __restrict__ hidden,
                                                 const float* __restrict__ lnw){
    extern __shared__ float sx[];
    float* rows = sx;               // 16*768
    float* rsq  = sx + 16*768;      // 16
    int b = blockIdx.y, q0 = blockIdx.x*16, t = threadIdx.x;
    const float* hrow = hidden + (size_t)(b*NQ+q0)*768;
    for (int idx = t; idx < 16*768; idx += 256) rows[idx] = hrow[idx];
    __syncthreads();
    { int r = t>>4, sub = t&15; float s = 0.f;
      for (int e = sub; e < 768; e += 16){ float v = rows[r*768+e]; s += v*v; }
      s += __shfl_xor_sync(~0u, s, 1);
      s += __shfl_xor_sync(~0u, s, 2);
      s += __shfl_xor_sync(~0u, s, 4);
      s += __shfl_xor_sync(~0u, s, 8);
      if (sub == 0) rsq[r] = rsqrtf(s*(1.f/48.f) + 1e-6f);
    }
    __syncthreads();
    __nv_bfloat16* dst = g_xfeat + (size_t)(b*NQ+q0)*DX;
    for (int idx = t; idx < 16*DX; idx += 256){
        int r = idx/DX, d = idx - r*DX;
        float val;
        if (d < DF){
            int js = d/48, in = d - js*48;
            val = rows[r*768 + in*16 + c_comps[js]] * rsq[r] * lnw[in];
        } else val = (d == DF) ? 1.f : 0.f;
        dst[idx] = __float2bfloat16(val);
    }
}

// ========== K1b: vprojT via cp.async pipelined subtiles =====================
__global__ void __launch_bounds__(256) k1b_vproj(){
    extern __shared__ float sm2[];
    float* w_s = sm2;             // 11520
    float* v_s = sm2 + 11520;     // 2 * 6144
    int sl = blockIdx.x, h = blockIdx.y, b = blockIdx.z, t = threadIdx.x;

    for (int idx = t; idx < 11520; idx += 256){
        int g = idx/2304, r = idx - g*2304;
        w_s[idx] = g_WoT[(g*384 + h*48)*48 + r];
    }
    int j = sl*256 + t;
    int o48 = j % 48, c = j / 48;
    int g = c_grade[c];
    const float* Vg = g_vtmp + (size_t)((b*HH+h)*16)*12288;
    u32 sb = smem_u32(v_s);
    const float* wp = w_s + g*2304 + o48;

    {   // stage s = 0
        const float* src = Vg;
        #pragma unroll
        for (int it = 0; it < 6; it++){
            int idx = t + 256*it;
            int row = idx>>1, part = idx&1;
            cp16(sb + (u32)(row*8 + part*4)*4, src + row*16 + part*4);
        }
        asm volatile("cp.async.commit_group;" ::: "memory");
    }

    for (int s = 0; s < 32; s++){
        asm volatile("cp.async.wait_group 0;" ::: "memory");
        __syncthreads();
        if (s + 1 < 32){
            const float* src = Vg + (size_t)((s+1)>>1)*12288 + ((s+1)&1)*8;
            int buf = (s+1)&1;
            #pragma unroll
            for (int it = 0; it < 6; it++){
                int idx = t + 256*it;
                int row = idx>>1, part = idx&1;
                cp16(sb + (u32)(buf*6144 + row*8 + part*4)*4, src + row*16 + part*4);
            }
            asm volatile("cp.async.commit_group;" ::: "memory");
        } else {
            asm volatile("cp.async.commit_group;" ::: "memory");
        }
        const float* vp0 = v_s + (s&1)*6144 + c*8;
        u64 acc[4] = {0ull, 0ull, 0ull, 0ull};
        #pragma unroll 8
        for (int i = 0; i < 48; i++){
            float w = wp[i*48];
            u64 w2 = pk2(w, w);
            const float* vp = vp0 + i*128;
            acc[0] = f2fma(*(const u64*)(vp    ), w2, acc[0]);
            acc[1] = f2fma(*(const u64*)(vp + 2), w2, acc[1]);
            acc[2] = f2fma(*(const u64*)(vp + 4), w2, acc[2]);
            acc[3] = f2fma(*(const u64*)(vp + 6), w2, acc[3]);
        }
        u32 r4[4];
        #pragma unroll
        for (int kp = 0; kp < 4; kp++){
            float lo, hi; upk2(acc[kp], lo, hi);
            r4[kp] = bf2(lo, hi);
        }
        __nv_bfloat16* dst = g_vprojT + (size_t)(b*768 + o48*16 + c)*2048
                           + h*256 + (s>>1)*16 + (s&1)*8;
        *(uint4*)dst = *(const uint4*)r4;
        __syncthreads();
    }
}

// ======= K2m: M[b,h][k][544] (bf16) — 512 CTAs, 32 keys each ================
__global__ void __launch_bounds__(256) k2m_M(const float* __restrict__ bq){
    __shared__ float kfT[48*34];
    __shared__ float ws [48*49];
    __shared__ float mT [48*34];
    __shared__ float kb32[32];
    __shared__ float ss32[32];
    int kt0 = blockIdx.x*32, h = blockIdx.y, b = blockIdx.z, t = threadIdx.x;
    size_t kbase = (size_t)((b*HH+h)*NK) + kt0;
    if (t < 32) ss32[t] = 0.f;

    for (int js = 0; js < 11; js++){
        int g = c_cg[js];
        __syncthreads();
        #pragma unroll
        for (int r = 0; r < 6; r++){
            int idx = t + 256*r;
            if (idx < 1536){
                int k = idx/48, j = idx - k*48;
                kfT[j*34 + k] = g_kfeatT[(kbase + k)*DFP + js*48 + j];
            }
        }
        #pragma unroll
        for (int r = 0; r < 9; r++){
            int idx = t + 256*r;
            if (idx < 2304){
                int c = idx/48, j = idx - c*48;
                ws[j*49 + c] = g_WqT[(g*48+c)*384 + h*48 + j];
            }
        }
        __syncthreads();
        if (js == 0 && t < 32){
            float s = 0.f;
            #pragma unroll 8
            for (int j = 0; j < 48; j++) s += bq[h*48+j]*kfT[j*34 + t];
            kb32[t] = s;
        }
        if (js >= 8 && t < 32){
            float s = 0.f;
            #pragma unroll 8
            for (int j = 0; j < 48; j++){ float v = kfT[j*34 + t]; s += v*v; }
            ss32[t] += s;
        }
        #pragma unroll
        for (int r = 0; r < 3; r++){
            int o = t + 256*r;
            int c = o >> 4, kp = o & 15;
            u64 acc = 0ull;
            #pragma unroll 8
            for (int j = 0; j < 48; j++){
                float w = ws[j*49 + c];
                acc = f2fma(*(const u64*)&kfT[j*34 + 2*kp], pk2(w, w), acc);
            }
            *(u64*)&mT[c*34 + 2*kp] = acc;
        }
        __syncthreads();
        #pragma unroll
        for (int r = 0; r < 6; r++){
            int idx = t + 256*r;
            if (idx < 1536){
                int k = idx/48, c = idx - k*48;
                g_M[(kbase + k)*DX + js*48 + c] = __float2bfloat16(mT[c*34 + k]);
            }
        }
    }
    __syncthreads();
    float sp = g_sp[h];
    #pragma unroll
    for (int r = 0; r < 2; r++){
        int idx = t + 256*r;
        int k = idx >> 4, cc = idx & 15;
        float v = (cc == 0) ? (kb32[k] - (12.f/sp)*ss32[k]) : 0.f;
        g_M[(kbase + k)*DX + DF + cc] = __float2bfloat16(v);
    }
}

// ============ bf16 GEMM core: 64 rows x 256 cols, ldmatrix + mma16816 =======
#define AROW 20
#define BOFF 1280
#define BUFU 6400

__device__ __forceinline__ void gemm_chunk(u32 base, float acc[4][4][4],
                                           int wid, u32 aofs, u32 bofs){
    #pragma unroll
    for (int k16 = 0; k16 < 2; k16++){
        int ko = k16*8;
        u32 au[4][4];
        #pragma unroll
        for (int mt = 0; mt < 4; mt++)
            ldsm4(au[mt][0], au[mt][1], au[mt][2], au[mt][3],
                  base + (u32)(mt*16*AROW + ko)*4 + aofs);
        u32 bu[4][2];
        ldsm4(bu[0][0], bu[0][1], bu[1][0], bu[1][1],
              base + (u32)(BOFF + wid*32*AROW + ko)*4 + bofs);
        ldsm4(bu[2][0], bu[2][1], bu[3][0], bu[3][1],
              base + (u32)(BOFF + (wid*32+16)*AROW + ko)*4 + bofs);
        #pragma unroll
        for (int mt = 0; mt < 4; mt++)
            #pragma unroll
            for (int nt8 = 0; nt8 < 4; nt8++)
                mma16816(acc[mt][nt8], au[mt], bu[nt8]);
    }
}

__device__ __forceinline__ void stage_tile(int t, u32 sb, const __nv_bfloat16* Ag,
                                           const __nv_bfloat16* Bg, int kc, int stride){
    { int row = t>>2, seg = t&3;
      cp16(sb + (u32)(row*AROW + seg*4)*4, Ag + (size_t)row*stride + kc*32 + seg*8); }
    #pragma unroll
    for (int it = 0; it < 4; it++){
        int i = t + 256*it, row = i>>2, seg = i&3;
        cp16(sb + (u32)(BOFF + row*AROW + seg*4)*4, Bg + (size_t)row*stride + kc*32 + seg*8);
    }
    asm volatile("cp.async.commit_group;" ::: "memory");
}

// ===================== K2b: bf16 mma logits + softmax ======================
__global__ void __launch_bounds__(256, 2) k2b_logits(){
    extern __shared__ u32 smp[];
    float* red  = (float*)(smp + 3*BUFU);
    float* rmax = red + 512;
    float* rsum = rmax + 64;
    int t = threadIdx.x, wid = t>>5, lane = t&31;
    int g = lane>>2, t4 = lane&3;
    int qt = blockIdx.x, h = blockIdx.y, b = blockIdx.z;

    u32 aofs = (u32)((((lane&7) + ((lane>>3)&1)*8)*AROW + ((lane>>4)&1)*4)*4);
    u32 bofs = (u32)(((((lane>>4)&1)*8 + (lane&7))*AROW + ((lane>>3)&1)*4)*4);

    const __nv_bfloat16* Ag = g_xfeat + (size_t)(b*NQ + qt*64)*DX;
    const __nv_bfloat16* Bg = g_M     + (size_t)((b*HH+h)*NK)*DX;
    u32 sb = smem_u32(smp);

    float acc[4][4][4];
    #pragma unroll
    for (int mt = 0; mt < 4; mt++)
        #pragma unroll
        for (int nt8 = 0; nt8 < 4; nt8++)
            #pragma unroll
            for (int r = 0; r < 4; r++) acc[mt][nt8][r] = 0.f;

    stage_tile(t, sb, Ag, Bg, 0, DX);
    stage_tile(t, sb + BUFU*4, Ag, Bg, 1, DX);
    for (int kc = 0; kc < 17; kc++){
        asm volatile("cp.async.wait_group 1;" ::: "memory");
        __syncthreads();
        if (kc + 2 < 17)
            stage_tile(t, sb + (u32)(((kc+2)%3)*BUFU)*4, Ag, Bg, kc+2, DX);
        else
            asm volatile("cp.async.commit_group;" ::: "memory");
        gemm_chunk(sb + (u32)((kc%3)*BUFU)*4, acc, wid, aofs, bofs);
    }

    __syncthreads();
    #pragma unroll
    for (int mt = 0; mt < 4; mt++)
        #pragma unroll
        for (int i = 0; i < 2; i++){
            float m = -1e30f;
            #pragma unroll
            for (int nt8 = 0; nt8 < 4; nt8++)
                m = fmaxf(m, fmaxf(acc[mt][nt8][2*i], acc[mt][nt8][2*i+1]));
            m = fmaxf(m, __shfl_xor_sync(~0u, m, 1));
            m = fmaxf(m, __shfl_xor_sync(~0u, m, 2));
            if (t4 == 0) red[(mt*16 + g + i*8)*8 + wid] = m;
        }
    __syncthreads();
    if (t < 64){
        float m = red[t*8];
        #pragma unroll
        for (int j = 1; j < 8; j++) m = fmaxf(m, red[t*8+j]);
        rmax[t] = m;
    }
    __syncthreads();
    #pragma unroll
    for (int mt = 0; mt < 4; mt++)
        #pragma unroll
        for (int i = 0; i < 2; i++){
            float mm = rmax[mt*16 + g + i*8];
            float s = 0.f;
            #pragma unroll
            for (int nt8 = 0; nt8 < 4; nt8++){
                float e0 = __expf(acc[mt][nt8][2*i]   - mm);
                float e1 = __expf(acc[mt][nt8][2*i+1] - mm);
                acc[mt][nt8][2*i] = e0; acc[mt][nt8][2*i+1] = e1;
                s += e0 + e1;
            }
            s += __shfl_xor_sync(~0u, s, 1);
            s += __shfl_xor_sync(~0u, s, 2);
            if (t4 == 0) red[(mt*16 + g + i*8)*8 + wid] = s;
        }
    __syncthreads();
    if (t < 64){
        float s = red[t*8];
        #pragma unroll
        for (int j = 1; j < 8; j++) s += red[t*8+j];
        rsum[t] = 1.f/s;
    }
    __syncthreads();
    #pragma unroll
    for (int mt = 0; mt < 4; mt++)
        #pragma unroll
        for (int i = 0; i < 2; i++){
            int row = mt*16 + g + i*8;
            float inv = rsum[row];
            __nv_bfloat16* dst = g_attn + (size_t)(b*NQ + qt*64 + row)*2048 + h*NK + wid*32;
            #pragma unroll
            for (int nt8 = 0; nt8 < 4; nt8++)
                *(u32*)(dst + nt8*8 + t4*2) = bf2(acc[mt][nt8][2*i]*inv,
                                                  acc[mt][nt8][2*i+1]*inv);
        }
}

// ===================== K3: bf16 mma attn @ vprojT + residual ================
__global__ void __launch_bounds__(256, 2) k3_av(const float* __restrict__ hidden,
                                                const float* __restrict__ bo,
                                                float* __restrict__ out){
    extern __shared__ u32 smp[];
    int t = threadIdx.x, wid = t>>5, lane = t&31;
    int g = lane>>2, t4 = lane&3;
    int nt = blockIdx.x, qt = blockIdx.y, b = blockIdx.z;

    u32 aofs = (u32)((((lane&7) + ((lane>>3)&1)*8)*AROW + ((lane>>4)&1)*4)*4);
    u32 bofs = (u32)(((((lane>>4)&1)*8 + (lane&7))*AROW + ((lane>>3)&1)*4)*4);

    const __nv_bfloat16* Ag = g_attn   + (size_t)(b*NQ + qt*64)*2048;
    const __nv_bfloat16* Bg = g_vprojT + (size_t)(b*768 + nt*256)*2048;
    u32 sb = smem_u32(smp);

    float acc[4][4][4];
    #pragma unroll
    for (int mt = 0; mt < 4; mt++)
        #pragma unroll
        for (int nt8 = 0; nt8 < 4; nt8++)
            #pragma unroll
            for (int r = 0; r < 4; r++) acc[mt][nt8][r] = 0.f;

    stage_tile(t, sb, Ag, Bg, 0, 2048);
    stage_tile(t, sb + BUFU*4, Ag, Bg, 1, 2048);
    for (int kc = 0; kc < 64; kc++){
        asm volatile("cp.async.wait_group 1;" ::: "memory");
        __syncthreads();
        if (kc + 2 < 64)
            stage_tile(t, sb + (u32)(((kc+2)%3)*BUFU)*4, Ag, Bg, kc+2, 2048);
        else
            asm volatile("cp.async.commit_group;" ::: "memory");
        gemm_chunk(sb + (u32)((kc%3)*BUFU)*4, acc, wid, aofs, bofs);
    }

    #pragma unroll
    for (int mt = 0; mt < 4; mt++)
        #pragma unroll
        for (int i = 0; i < 2; i++){
            int row = qt*64 + mt*16 + g + i*8;
            const float* hb = hidden + (size_t)(b*NQ + row)*768;
            float*       ob = out    + (size_t)(b*NQ + row)*768;
            #pragma unroll
            for (int nt8 = 0; nt8 < 4; nt8++){
                int col = nt*256 + wid*32 + nt8*8 + t4*2;
                float2 hv = *(const float2*)(hb + col);
                float vx = acc[mt][nt8][2*i]   + hv.x;
                float vy = acc[mt][nt8][2*i+1] + hv.y;
                if ((col & 15) == 0) vx += bo[col >> 4];
                *(float2*)(ob + col) = make_float2(vx, vy);
            }
        }
}

// ===========================================================================
extern "C" void kernel_launch(void* const* d_in, const int* in_sizes, int n_in,
                              void* d_out, int out_size){
    const float* hidden = (const float*)d_in[0];
    const float* vision = (const float*)d_in[1];
    const float* lnw    = (const float*)d_in[2];
    const float* Wq     = (const float*)d_in[3];
    const float* bq     = (const float*)d_in[4];
    const float* Wkv    = (const float*)d_in[5];
    const float* bkv    = (const float*)d_in[6];
    const float* Wo     = (const float*)d_in[7];
    const float* bo     = (const float*)d_in[8];
    const float* daa    = (const float*)d_in[9];
    float* out = (float*)d_out;

    const int s1x = (16*768)*4;                       // 49152
    const int s1m = (320*KROW)*4;                     // 35840
    const int s2x = (16*768 + 16)*4;
    const int s1b = (11520 + 2*6144)*4;               // 95232
    const int s2b = (3*BUFU)*4 + (512 + 64 + 64)*4;   // 79360
    const int s3  = (3*BUFU)*4;                        // 76800
    cudaFuncSetAttribute(k1x_xv,    cudaFuncAttributeMaxDynamicSharedMemorySize, s1x);
    cudaFuncSetAttribute(k1m_kv,    cudaFuncAttributeMaxDynamicSharedMemorySize, s1m);
    cudaFuncSetAttribute(k2x_xfeat, cudaFuncAttributeMaxDynamicSharedMemorySize, s2x);
    cudaFuncSetAttribute(k1b_vproj, cudaFuncAttributeMaxDynamicSharedMemorySize, s1b);
    cudaFuncSetAttribute(k2b_logits,cudaFuncAttributeMaxDynamicSharedMemorySize, s2b);
    cudaFuncSetAttribute(k3_av,     cudaFuncAttributeMaxDynamicSharedMemorySize, s3);

    k0a_prep  <<<64, 256>>>(Wq, Wo, daa);                       // 0
    k1x_xv    <<<dim3(NK/16, BB), 256, s1x>>>(vision);          // 1
    k0b_prep  <<<64, 256>>>(Wkv);                               // 2
    k1m_kv    <<<dim3(12, 16, BB), 256, s1m>>>(bkv);            // 3 (profiled)
    k2x_xfeat <<<dim3(NQ/16, BB), 256, s2x>>>(hidden, lnw);     // 4
    k1b_vproj <<<dim3(3, HH, BB), 256, s1b>>>();                // 5
    k2m_M     <<<dim3(NK/32, HH, BB), 256>>>(bq);               // 6
    k2b_logits<<<dim3(NQ/64, HH, BB), 256, s2b>>>();            // 7
    k3_av     <<<dim3(3, NQ/64, BB), 256, s3>>>(hidden, bo, out); // 8
}